// round 5
// baseline (speedup 1.0000x reference)
#include <cuda_runtime.h>
#include <math.h>
#include <stdint.h>

#define N_NODES 50000
#define E_EDGES 800000
#define NFEAT   512
#define NHID    128
#define NCLASS  40

// ---------------- scratch (device globals; no allocation) ----------------
__device__ __align__(16) float g_XW1[N_NODES * NHID];   // x @ W1
__device__ __align__(16) float g_XW3[N_NODES * NHID];   // x @ W3
__device__ __align__(16) float g_T1[N_NODES * NHID];    // spmm(adj , xW1)
__device__ __align__(16) float g_T3[N_NODES * NHID];    // spmm(adj2, xW3)
__device__ __align__(16) float g_H1[N_NODES * NCLASS];  // relu(T1+b1) @ W2
__device__ __align__(16) float g_H2[N_NODES * NCLASS];  // relu(T3+b3) @ W4
__device__ __align__(16) float g_O1[N_NODES * NCLASS];  // spmm(adj , H1)
__device__ __align__(16) float g_O2[N_NODES * NCLASS];  // spmm(adj2, H2)

// CSR scratch (per edge list)
__device__ int   g_cnt1[N_NODES],     g_cnt2[N_NODES];
__device__ int   g_rp1[N_NODES + 1],  g_rp2[N_NODES + 1];
__device__ int   g_cur1[N_NODES],     g_cur2[N_NODES];
__device__ int   g_es1[E_EDGES],      g_es2[E_EDGES];
__device__ float g_evv1[E_EDGES],     g_evv2[E_EDGES];

// ---------------- CSR build ----------------
__global__ void zero_cnt_kernel() {
    int i = blockIdx.x * blockDim.x + threadIdx.x;
    if (i < N_NODES) { g_cnt1[i] = 0; g_cnt2[i] = 0; }
}

__global__ void hist_kernel(const int* __restrict__ ei1,
                            const int* __restrict__ ei2) {
    int e = blockIdx.x * blockDim.x + threadIdx.x;
    if (e >= E_EDGES) return;
    int* cnt = blockIdx.y ? g_cnt2 : g_cnt1;
    const int* ei = blockIdx.y ? ei2 : ei1;
    atomicAdd(&cnt[ei[E_EDGES + e]], 1);
}

// one block per list; chunked exclusive scan over 50k counters
__global__ __launch_bounds__(1024) void scan_kernel() {
    const int list = blockIdx.x;
    __shared__ int sums[1024];
    const int tid = threadIdx.x;
    const int CHUNK = (N_NODES + 1023) / 1024;   // 49
    int begin = tid * CHUNK;
    int endi = begin + CHUNK; if (endi > N_NODES) endi = N_NODES;
    const int* cnt = list ? g_cnt2 : g_cnt1;
    int* rp  = list ? g_rp2  : g_rp1;
    int* cur = list ? g_cur2 : g_cur1;

    int s = 0;
    for (int i = begin; i < endi; i++) s += cnt[i];
    sums[tid] = s;
    __syncthreads();
    // inclusive Hillis-Steele
    for (int off = 1; off < 1024; off <<= 1) {
        int v = sums[tid];
        int add = (tid >= off) ? sums[tid - off] : 0;
        __syncthreads();
        sums[tid] = v + add;
        __syncthreads();
    }
    int run = (tid == 0) ? 0 : sums[tid - 1];
    for (int i = begin; i < endi; i++) {
        int c = cnt[i];
        rp[i] = run; cur[i] = run;
        run += c;
    }
    if (tid == 1023) rp[N_NODES] = E_EDGES;
}

__global__ void scatter_kernel(const int* __restrict__ ei1,
                               const float* __restrict__ ev1,
                               const int* __restrict__ ei2,
                               const float* __restrict__ ev2) {
    int e = blockIdx.x * blockDim.x + threadIdx.x;
    if (e >= E_EDGES) return;
    const int sel = blockIdx.y;
    const int* ei = sel ? ei2 : ei1;
    const float* ev = sel ? ev2 : ev1;
    int* cur = sel ? g_cur2 : g_cur1;
    int* es  = sel ? g_es2  : g_es1;
    float* evs = sel ? g_evv2 : g_evv1;
    int s = ei[e];
    int d = ei[E_EDGES + e];
    int pos = atomicAdd(&cur[d], 1);
    es[pos] = s;
    evs[pos] = ev[e];
}

// ---------------- helpers ----------------
__device__ __forceinline__ float to_tf32(float f) {
    float r;
    asm("cvt.rna.tf32.f32 %0, %1;" : "=f"(r) : "f"(f));
    return r;
}

// ---------------- GEMM1 (TF32 tensor cores) ----------------
__global__ __launch_bounds__(256) void gemm512_tf32_kernel(
        const float* __restrict__ X,
        const float* __restrict__ W1,
        const float* __restrict__ W3) {
    const float* W   = blockIdx.y ? W3    : W1;
    float*       Out = blockIdx.y ? g_XW3 : g_XW1;

    __shared__ float As[32][132];
    __shared__ float Bs[32][132];

    const int tid  = threadIdx.x;
    const int lane = tid & 31;
    const int wid  = tid >> 5;
    const int mBase = (wid >> 1) * 32;
    const int nBase = (wid & 1) * 64;
    const int q = lane >> 2;
    const int c = lane & 3;
    const int rowBase = blockIdx.x * 128;

    float acc[2][8][4];
#pragma unroll
    for (int i = 0; i < 2; i++)
#pragma unroll
        for (int j = 0; j < 8; j++)
#pragma unroll
            for (int t = 0; t < 4; t++) acc[i][j][t] = 0.f;

    for (int k0 = 0; k0 < NFEAT; k0 += 32) {
#pragma unroll
        for (int i = 0; i < 4; i++) {
            int li = tid + i * 256;
            int r  = li >> 3;
            int kc = (li & 7) << 2;
            int grow = rowBase + r;
            float4 v = make_float4(0.f, 0.f, 0.f, 0.f);
            if (grow < N_NODES)
                v = *reinterpret_cast<const float4*>(X + (size_t)grow * NFEAT + k0 + kc);
            As[kc + 0][r] = to_tf32(v.x);
            As[kc + 1][r] = to_tf32(v.y);
            As[kc + 2][r] = to_tf32(v.z);
            As[kc + 3][r] = to_tf32(v.w);
        }
#pragma unroll
        for (int i = 0; i < 4; i++) {
            int li = tid + i * 256;
            int r  = li >> 5;
            int nc = (li & 31) << 2;
            float4 v = *reinterpret_cast<const float4*>(W + (size_t)(k0 + r) * NHID + nc);
            v.x = to_tf32(v.x); v.y = to_tf32(v.y);
            v.z = to_tf32(v.z); v.w = to_tf32(v.w);
            *reinterpret_cast<float4*>(&Bs[r][nc]) = v;
        }
        __syncthreads();

#pragma unroll
        for (int kk = 0; kk < 32; kk += 8) {
            uint32_t af[2][4];
#pragma unroll
            for (int i = 0; i < 2; i++) {
                int rA = mBase + i * 16 + q;
                af[i][0] = __float_as_uint(As[kk + c    ][rA    ]);
                af[i][1] = __float_as_uint(As[kk + c    ][rA + 8]);
                af[i][2] = __float_as_uint(As[kk + c + 4][rA    ]);
                af[i][3] = __float_as_uint(As[kk + c + 4][rA + 8]);
            }
            uint32_t bf[8][2];
#pragma unroll
            for (int j = 0; j < 8; j++) {
                int nC = nBase + j * 8 + q;
                bf[j][0] = __float_as_uint(Bs[kk + c    ][nC]);
                bf[j][1] = __float_as_uint(Bs[kk + c + 4][nC]);
            }
#pragma unroll
            for (int i = 0; i < 2; i++)
#pragma unroll
                for (int j = 0; j < 8; j++) {
                    asm volatile(
                        "mma.sync.aligned.m16n8k8.row.col.f32.tf32.tf32.f32 "
                        "{%0,%1,%2,%3}, {%4,%5,%6,%7}, {%8,%9}, {%0,%1,%2,%3};"
                        : "+f"(acc[i][j][0]), "+f"(acc[i][j][1]),
                          "+f"(acc[i][j][2]), "+f"(acc[i][j][3])
                        : "r"(af[i][0]), "r"(af[i][1]), "r"(af[i][2]), "r"(af[i][3]),
                          "r"(bf[j][0]), "r"(bf[j][1]));
                }
        }
        __syncthreads();
    }

#pragma unroll
    for (int i = 0; i < 2; i++) {
        int r0 = rowBase + mBase + i * 16 + q;
        int r1 = r0 + 8;
#pragma unroll
        for (int j = 0; j < 8; j++) {
            int col = nBase + j * 8 + 2 * c;
            if (r0 < N_NODES) {
                Out[(size_t)r0 * NHID + col    ] = acc[i][j][0];
                Out[(size_t)r0 * NHID + col + 1] = acc[i][j][1];
            }
            if (r1 < N_NODES) {
                Out[(size_t)r1 * NHID + col    ] = acc[i][j][2];
                Out[(size_t)r1 * NHID + col + 1] = acc[i][j][3];
            }
        }
    }
}

// ---------------- SPMM F=128 via CSR: warp per dst ----------------
__global__ void spmm128_csr_kernel() {
    int gw = (blockIdx.x * blockDim.x + threadIdx.x) >> 5;
    if (gw >= N_NODES) return;
    const int lane = threadIdx.x & 31;
    const int sel = blockIdx.y;
    const int* rp = sel ? g_rp2 : g_rp1;
    const int* es = sel ? g_es2 : g_es1;
    const float* evs = sel ? g_evv2 : g_evv1;
    const float4* in = sel ? reinterpret_cast<const float4*>(g_XW3)
                           : reinterpret_cast<const float4*>(g_XW1);
    float4* out = sel ? reinterpret_cast<float4*>(g_T3)
                      : reinterpret_cast<float4*>(g_T1);

    int start = rp[gw];
    int end   = rp[gw + 1];
    float4 acc = make_float4(0.f, 0.f, 0.f, 0.f);

    for (int j = start; j < end; j += 32) {
        int m = end - j;
        int iter = m < 32 ? m : 32;
        int s = 0; float v = 0.f;
        if (lane < iter) { s = es[j + lane]; v = evs[j + lane]; }
        for (int k = 0; k < iter; k++) {
            int   ss = __shfl_sync(0xffffffffu, s, k);
            float vv = __shfl_sync(0xffffffffu, v, k);
            float4 h = in[(size_t)ss * 32 + lane];
            acc.x += vv * h.x; acc.y += vv * h.y;
            acc.z += vv * h.z; acc.w += vv * h.w;
        }
    }
    out[(size_t)gw * 32 + lane] = acc;
}

// ---------------- GEMM2: H = relu(T + b) @ W  (K=128, N=40) ----------------
__global__ void gemm2_kernel(const float* __restrict__ b1,
                             const float* __restrict__ W2,
                             const float* __restrict__ b3,
                             const float* __restrict__ W4) {
    const int sel = blockIdx.y;
    const float* T = sel ? g_T3 : g_T1;
    const float* b = sel ? b3 : b1;
    const float* W = sel ? W4 : W2;
    float*      Out = sel ? g_H2 : g_H1;

    __shared__ float Ws[NHID][NCLASS];
    __shared__ float bs[NHID];
    __shared__ float Ts[64][17];

    const int tid = threadIdx.x;
    for (int i = tid; i < NHID * NCLASS; i += 256)
        reinterpret_cast<float*>(Ws)[i] = W[i];
    if (tid < NHID) bs[tid] = b[tid];
    __syncthreads();

    const int rowBase = blockIdx.x * 64;
    const int row = tid & 63;
    const int cg = tid >> 6;
    const int col0 = cg * 10;
    const int grow = rowBase + row;

    float acc[10];
#pragma unroll
    for (int j = 0; j < 10; j++) acc[j] = 0.f;

    for (int kb = 0; kb < NHID; kb += 16) {
#pragma unroll
        for (int i = 0; i < 4; i++) {
            int li = tid + i * 256;
            int r = li >> 4;
            int c = li & 15;
            int gr = rowBase + r;
            float v = 0.f;
            if (gr < N_NODES) v = T[(size_t)gr * NHID + kb + c];
            Ts[r][c] = fmaxf(v + bs[kb + c], 0.f);
        }
        __syncthreads();
#pragma unroll
        for (int kk = 0; kk < 16; kk++) {
            float h = Ts[row][kk];
#pragma unroll
            for (int j = 0; j < 10; j++)
                acc[j] += h * Ws[kb + kk][col0 + j];
        }
        __syncthreads();
    }

    if (grow < N_NODES) {
#pragma unroll
        for (int j = 0; j < 10; j++)
            Out[(size_t)grow * NCLASS + col0 + j] = acc[j];
    }
}

// ---------------- SPMM F=40 via CSR: warp per dst (float2 per lane) ------
__global__ void spmm40_csr_kernel() {
    int gw = (blockIdx.x * blockDim.x + threadIdx.x) >> 5;
    if (gw >= N_NODES) return;
    const int lane = threadIdx.x & 31;
    const int sel = blockIdx.y;
    const int* rp = sel ? g_rp2 : g_rp1;
    const int* es = sel ? g_es2 : g_es1;
    const float* evs = sel ? g_evv2 : g_evv1;
    const float2* in = sel ? reinterpret_cast<const float2*>(g_H2)
                           : reinterpret_cast<const float2*>(g_H1);
    float2* out = sel ? reinterpret_cast<float2*>(g_O2)
                      : reinterpret_cast<float2*>(g_O1);

    int start = rp[gw];
    int end   = rp[gw + 1];
    float2 acc = make_float2(0.f, 0.f);

    for (int j = start; j < end; j += 32) {
        int m = end - j;
        int iter = m < 32 ? m : 32;
        int s = 0; float v = 0.f;
        if (lane < iter) { s = es[j + lane]; v = evs[j + lane]; }
        for (int k = 0; k < iter; k++) {
            int   ss = __shfl_sync(0xffffffffu, s, k);
            float vv = __shfl_sync(0xffffffffu, v, k);
            if (lane < 20) {
                float2 h = in[(size_t)ss * 20 + lane];
                acc.x += vv * h.x;
                acc.y += vv * h.y;
            }
        }
    }
    if (lane < 20) out[(size_t)gw * 20 + lane] = acc;
}

// ---------------- fusion: gate + blend + log_softmax ----------------
__global__ void fuse_kernel(const float* __restrict__ b2,
                            const float* __restrict__ b4,
                            const float* __restrict__ Wl,
                            const float* __restrict__ bl,
                            float* __restrict__ out) {
    __shared__ float Wls[2 * NCLASS][NCLASS];
    __shared__ float b2s[NCLASS], b4s[NCLASS], bls[NCLASS];
    __shared__ float catS[8][2 * NCLASS];

    const int tid = threadIdx.x;
    const int lane = tid & 31;
    const int w = tid >> 5;

    for (int i = tid; i < 2 * NCLASS * NCLASS; i += 256)
        reinterpret_cast<float*>(Wls)[i] = Wl[i];
    if (tid < NCLASS) {
        b2s[tid] = b2[tid];
        b4s[tid] = b4[tid];
        bls[tid] = bl[tid];
    }
    __syncthreads();

    const int n = blockIdx.x * 8 + w;
    if (n >= N_NODES) return;

    for (int i = lane; i < NCLASS; i += 32) {
        catS[w][i]          = g_O1[(size_t)n * NCLASS + i] + b2s[i];
        catS[w][NCLASS + i] = g_O2[(size_t)n * NCLASS + i] + b4s[i];
    }
    __syncwarp();

    float v0, v1 = -1e30f;
    {
        int j = lane;
        float g = bls[j];
#pragma unroll
        for (int i = 0; i < 2 * NCLASS; i++) g += catS[w][i] * Wls[i][j];
        g = 1.f / (1.f + expf(-g));
        v0 = g * catS[w][j] + (1.f - g) * catS[w][NCLASS + j];
    }
    if (lane < 8) {
        int j = 32 + lane;
        float g = bls[j];
#pragma unroll
        for (int i = 0; i < 2 * NCLASS; i++) g += catS[w][i] * Wls[i][j];
        g = 1.f / (1.f + expf(-g));
        v1 = g * catS[w][j] + (1.f - g) * catS[w][NCLASS + j];
    }

    float m = fmaxf(v0, v1);
#pragma unroll
    for (int off = 16; off > 0; off >>= 1)
        m = fmaxf(m, __shfl_xor_sync(0xffffffffu, m, off));
    float s = expf(v0 - m) + (lane < 8 ? expf(v1 - m) : 0.f);
#pragma unroll
    for (int off = 16; off > 0; off >>= 1)
        s += __shfl_xor_sync(0xffffffffu, s, off);
    float ls = m + logf(s);

    out[(size_t)n * NCLASS + lane] = v0 - ls;
    if (lane < 8) out[(size_t)n * NCLASS + 32 + lane] = v1 - ls;
}

// ---------------- launch ----------------
extern "C" void kernel_launch(void* const* d_in, const int* in_sizes, int n_in,
                              void* d_out, int out_size) {
    const float* x   = (const float*)d_in[0];
    const int*   ei1 = (const int*)d_in[1];
    const float* ev1 = (const float*)d_in[2];
    const int*   ei2 = (const int*)d_in[3];
    const float* ev2 = (const float*)d_in[4];
    const float* W1  = (const float*)d_in[5];
    const float* b1  = (const float*)d_in[6];
    const float* W2  = (const float*)d_in[7];
    const float* b2  = (const float*)d_in[8];
    const float* W3  = (const float*)d_in[9];
    const float* b3  = (const float*)d_in[10];
    const float* W4  = (const float*)d_in[11];
    const float* b4  = (const float*)d_in[12];
    const float* Wl  = (const float*)d_in[13];
    const float* bl  = (const float*)d_in[14];
    float* out = (float*)d_out;

    const int EB = (E_EDGES + 255) / 256;

    // ---- CSR build for both edge lists ----
    zero_cnt_kernel<<<(N_NODES + 255) / 256, 256>>>();
    hist_kernel<<<dim3(EB, 2), 256>>>(ei1, ei2);
    scan_kernel<<<2, 1024>>>();
    scatter_kernel<<<dim3(EB, 2), 256>>>(ei1, ev1, ei2, ev2);

    // ---- GEMM1 (runs while CSR builds are independent of it — same stream,
    //      but GEMM1 doesn't depend on CSR; order chosen so scatter hides) --
    gemm512_tf32_kernel<<<dim3((N_NODES + 127) / 128, 2), 256>>>(x, W1, W3);

    // ---- SPMM over 128 features (CSR, no atomics) ----
    {
        int blocks = (N_NODES * 32 + 255) / 256;
        spmm128_csr_kernel<<<dim3(blocks, 2), 256>>>();
    }

    // ---- GEMM2 for both towers (relu+bias fused) ----
    gemm2_kernel<<<dim3((N_NODES + 63) / 64, 2), 256>>>(b1, W2, b3, W4);

    // ---- SPMM over 40 features (CSR, no atomics) ----
    {
        int blocks = (N_NODES * 32 + 255) / 256;
        spmm40_csr_kernel<<<dim3(blocks, 2), 256>>>();
    }

    // ---- gated fusion + log_softmax ----
    fuse_kernel<<<(N_NODES + 7) / 8, 256>>>(b2, b4, Wl, bl, out);
}

// round 6
// speedup vs baseline: 1.0055x; 1.0055x over previous
#include <cuda_runtime.h>
#include <math.h>
#include <stdint.h>

#define N_NODES 50000
#define E_EDGES 800000
#define NFEAT   512
#define NHID    128
#define NCLASS  40

// ---------------- scratch (device globals; no allocation) ----------------
__device__ __align__(16) float g_XW1[N_NODES * NHID];   // x @ W1
__device__ __align__(16) float g_XW3[N_NODES * NHID];   // x @ W3
__device__ __align__(16) float g_T1[N_NODES * NHID];    // spmm(adj , xW1)
__device__ __align__(16) float g_T3[N_NODES * NHID];    // spmm(adj2, xW3)
__device__ __align__(16) float g_H1[N_NODES * NCLASS];  // relu(T1+b1) @ W2
__device__ __align__(16) float g_H2[N_NODES * NCLASS];  // relu(T3+b3) @ W4
__device__ __align__(16) float g_O1[N_NODES * NCLASS];  // spmm(adj , H1)
__device__ __align__(16) float g_O2[N_NODES * NCLASS];  // spmm(adj2, H2)

// CSR scratch (per edge list)
__device__ int   g_cnt1[N_NODES],     g_cnt2[N_NODES];
__device__ int   g_rp1[N_NODES + 1],  g_rp2[N_NODES + 1];
__device__ int   g_cur1[N_NODES],     g_cur2[N_NODES];
__device__ int   g_es1[E_EDGES],      g_es2[E_EDGES];
__device__ float g_evv1[E_EDGES],     g_evv2[E_EDGES];

// ---------------- CSR build ----------------
__global__ void zero_cnt_kernel() {
    int i = blockIdx.x * blockDim.x + threadIdx.x;
    if (i < N_NODES) { g_cnt1[i] = 0; g_cnt2[i] = 0; }
}

__global__ void hist_kernel(const int* __restrict__ ei1,
                            const int* __restrict__ ei2) {
    int e = blockIdx.x * blockDim.x + threadIdx.x;
    if (e >= E_EDGES) return;
    int* cnt = blockIdx.y ? g_cnt2 : g_cnt1;
    const int* ei = blockIdx.y ? ei2 : ei1;
    atomicAdd(&cnt[ei[E_EDGES + e]], 1);
}

// one block per list; chunked exclusive scan over 50k counters
__global__ __launch_bounds__(1024) void scan_kernel() {
    const int list = blockIdx.x;
    __shared__ int sums[1024];
    const int tid = threadIdx.x;
    const int CHUNK = (N_NODES + 1023) / 1024;   // 49
    int begin = tid * CHUNK;
    int endi = begin + CHUNK; if (endi > N_NODES) endi = N_NODES;
    const int* cnt = list ? g_cnt2 : g_cnt1;
    int* rp  = list ? g_rp2  : g_rp1;
    int* cur = list ? g_cur2 : g_cur1;

    int s = 0;
    for (int i = begin; i < endi; i++) s += cnt[i];
    sums[tid] = s;
    __syncthreads();
    // inclusive Hillis-Steele
    for (int off = 1; off < 1024; off <<= 1) {
        int v = sums[tid];
        int add = (tid >= off) ? sums[tid - off] : 0;
        __syncthreads();
        sums[tid] = v + add;
        __syncthreads();
    }
    int run = (tid == 0) ? 0 : sums[tid - 1];
    for (int i = begin; i < endi; i++) {
        int c = cnt[i];
        rp[i] = run; cur[i] = run;
        run += c;
    }
    if (tid == 1023) rp[N_NODES] = E_EDGES;
}

__global__ void scatter_kernel(const int* __restrict__ ei1,
                               const float* __restrict__ ev1,
                               const int* __restrict__ ei2,
                               const float* __restrict__ ev2) {
    int e = blockIdx.x * blockDim.x + threadIdx.x;
    if (e >= E_EDGES) return;
    const int sel = blockIdx.y;
    const int* ei = sel ? ei2 : ei1;
    const float* ev = sel ? ev2 : ev1;
    int* cur = sel ? g_cur2 : g_cur1;
    int* es  = sel ? g_es2  : g_es1;
    float* evs = sel ? g_evv2 : g_evv1;
    int s = ei[e];
    int d = ei[E_EDGES + e];
    int pos = atomicAdd(&cur[d], 1);
    es[pos] = s;
    evs[pos] = ev[e];
}

// ---------------- helpers ----------------
__device__ __forceinline__ float to_tf32(float f) {
    float r;
    asm("cvt.rna.tf32.f32 %0, %1;" : "=f"(r) : "f"(f));
    return r;
}

// ---------------- GEMM1 (TF32 tensor cores) ----------------
__global__ __launch_bounds__(256) void gemm512_tf32_kernel(
        const float* __restrict__ X,
        const float* __restrict__ W1,
        const float* __restrict__ W3) {
    const float* W   = blockIdx.y ? W3    : W1;
    float*       Out = blockIdx.y ? g_XW3 : g_XW1;

    __shared__ float As[32][132];
    __shared__ float Bs[32][132];

    const int tid  = threadIdx.x;
    const int lane = tid & 31;
    const int wid  = tid >> 5;
    const int mBase = (wid >> 1) * 32;
    const int nBase = (wid & 1) * 64;
    const int q = lane >> 2;
    const int c = lane & 3;
    const int rowBase = blockIdx.x * 128;

    float acc[2][8][4];
#pragma unroll
    for (int i = 0; i < 2; i++)
#pragma unroll
        for (int j = 0; j < 8; j++)
#pragma unroll
            for (int t = 0; t < 4; t++) acc[i][j][t] = 0.f;

    for (int k0 = 0; k0 < NFEAT; k0 += 32) {
#pragma unroll
        for (int i = 0; i < 4; i++) {
            int li = tid + i * 256;
            int r  = li >> 3;
            int kc = (li & 7) << 2;
            int grow = rowBase + r;
            float4 v = make_float4(0.f, 0.f, 0.f, 0.f);
            if (grow < N_NODES)
                v = *reinterpret_cast<const float4*>(X + (size_t)grow * NFEAT + k0 + kc);
            As[kc + 0][r] = to_tf32(v.x);
            As[kc + 1][r] = to_tf32(v.y);
            As[kc + 2][r] = to_tf32(v.z);
            As[kc + 3][r] = to_tf32(v.w);
        }
#pragma unroll
        for (int i = 0; i < 4; i++) {
            int li = tid + i * 256;
            int r  = li >> 5;
            int nc = (li & 31) << 2;
            float4 v = *reinterpret_cast<const float4*>(W + (size_t)(k0 + r) * NHID + nc);
            v.x = to_tf32(v.x); v.y = to_tf32(v.y);
            v.z = to_tf32(v.z); v.w = to_tf32(v.w);
            *reinterpret_cast<float4*>(&Bs[r][nc]) = v;
        }
        __syncthreads();

#pragma unroll
        for (int kk = 0; kk < 32; kk += 8) {
            uint32_t af[2][4];
#pragma unroll
            for (int i = 0; i < 2; i++) {
                int rA = mBase + i * 16 + q;
                af[i][0] = __float_as_uint(As[kk + c    ][rA    ]);
                af[i][1] = __float_as_uint(As[kk + c    ][rA + 8]);
                af[i][2] = __float_as_uint(As[kk + c + 4][rA    ]);
                af[i][3] = __float_as_uint(As[kk + c + 4][rA + 8]);
            }
            uint32_t bf[8][2];
#pragma unroll
            for (int j = 0; j < 8; j++) {
                int nC = nBase + j * 8 + q;
                bf[j][0] = __float_as_uint(Bs[kk + c    ][nC]);
                bf[j][1] = __float_as_uint(Bs[kk + c + 4][nC]);
            }
#pragma unroll
            for (int i = 0; i < 2; i++)
#pragma unroll
                for (int j = 0; j < 8; j++) {
                    asm volatile(
                        "mma.sync.aligned.m16n8k8.row.col.f32.tf32.tf32.f32 "
                        "{%0,%1,%2,%3}, {%4,%5,%6,%7}, {%8,%9}, {%0,%1,%2,%3};"
                        : "+f"(acc[i][j][0]), "+f"(acc[i][j][1]),
                          "+f"(acc[i][j][2]), "+f"(acc[i][j][3])
                        : "r"(af[i][0]), "r"(af[i][1]), "r"(af[i][2]), "r"(af[i][3]),
                          "r"(bf[j][0]), "r"(bf[j][1]));
                }
        }
        __syncthreads();
    }

#pragma unroll
    for (int i = 0; i < 2; i++) {
        int r0 = rowBase + mBase + i * 16 + q;
        int r1 = r0 + 8;
#pragma unroll
        for (int j = 0; j < 8; j++) {
            int col = nBase + j * 8 + 2 * c;
            if (r0 < N_NODES) {
                Out[(size_t)r0 * NHID + col    ] = acc[i][j][0];
                Out[(size_t)r0 * NHID + col + 1] = acc[i][j][1];
            }
            if (r1 < N_NODES) {
                Out[(size_t)r1 * NHID + col    ] = acc[i][j][2];
                Out[(size_t)r1 * NHID + col + 1] = acc[i][j][3];
            }
        }
    }
}

// ---------------- SPMM F=128 via CSR: warp per dst ----------------
__global__ void spmm128_csr_kernel() {
    int gw = (blockIdx.x * blockDim.x + threadIdx.x) >> 5;
    if (gw >= N_NODES) return;
    const int lane = threadIdx.x & 31;
    const int sel = blockIdx.y;
    const int* rp = sel ? g_rp2 : g_rp1;
    const int* es = sel ? g_es2 : g_es1;
    const float* evs = sel ? g_evv2 : g_evv1;
    const float4* in = sel ? reinterpret_cast<const float4*>(g_XW3)
                           : reinterpret_cast<const float4*>(g_XW1);
    float4* out = sel ? reinterpret_cast<float4*>(g_T3)
                      : reinterpret_cast<float4*>(g_T1);

    int start = rp[gw];
    int end   = rp[gw + 1];
    float4 acc = make_float4(0.f, 0.f, 0.f, 0.f);

    for (int j = start; j < end; j += 32) {
        int m = end - j;
        int iter = m < 32 ? m : 32;
        int s = 0; float v = 0.f;
        if (lane < iter) { s = es[j + lane]; v = evs[j + lane]; }
        for (int k = 0; k < iter; k++) {
            int   ss = __shfl_sync(0xffffffffu, s, k);
            float vv = __shfl_sync(0xffffffffu, v, k);
            float4 h = in[(size_t)ss * 32 + lane];
            acc.x += vv * h.x; acc.y += vv * h.y;
            acc.z += vv * h.z; acc.w += vv * h.w;
        }
    }
    out[(size_t)gw * 32 + lane] = acc;
}

// ---------------- GEMM2: H = relu(T + b) @ W  (K=128, N=40) ----------------
__global__ void gemm2_kernel(const float* __restrict__ b1,
                             const float* __restrict__ W2,
                             const float* __restrict__ b3,
                             const float* __restrict__ W4) {
    const int sel = blockIdx.y;
    const float* T = sel ? g_T3 : g_T1;
    const float* b = sel ? b3 : b1;
    const float* W = sel ? W4 : W2;
    float*      Out = sel ? g_H2 : g_H1;

    __shared__ float Ws[NHID][NCLASS];
    __shared__ float bs[NHID];
    __shared__ float Ts[64][17];

    const int tid = threadIdx.x;
    for (int i = tid; i < NHID * NCLASS; i += 256)
        reinterpret_cast<float*>(Ws)[i] = W[i];
    if (tid < NHID) bs[tid] = b[tid];
    __syncthreads();

    const int rowBase = blockIdx.x * 64;
    const int row = tid & 63;
    const int cg = tid >> 6;
    const int col0 = cg * 10;
    const int grow = rowBase + row;

    float acc[10];
#pragma unroll
    for (int j = 0; j < 10; j++) acc[j] = 0.f;

    for (int kb = 0; kb < NHID; kb += 16) {
#pragma unroll
        for (int i = 0; i < 4; i++) {
            int li = tid + i * 256;
            int r = li >> 4;
            int c = li & 15;
            int gr = rowBase + r;
            float v = 0.f;
            if (gr < N_NODES) v = T[(size_t)gr * NHID + kb + c];
            Ts[r][c] = fmaxf(v + bs[kb + c], 0.f);
        }
        __syncthreads();
#pragma unroll
        for (int kk = 0; kk < 16; kk++) {
            float h = Ts[row][kk];
#pragma unroll
            for (int j = 0; j < 10; j++)
                acc[j] += h * Ws[kb + kk][col0 + j];
        }
        __syncthreads();
    }

    if (grow < N_NODES) {
#pragma unroll
        for (int j = 0; j < 10; j++)
            Out[(size_t)grow * NCLASS + col0 + j] = acc[j];
    }
}

// ---------------- SPMM F=40 via CSR: warp per dst (float2 per lane) ------
__global__ void spmm40_csr_kernel() {
    int gw = (blockIdx.x * blockDim.x + threadIdx.x) >> 5;
    if (gw >= N_NODES) return;
    const int lane = threadIdx.x & 31;
    const int sel = blockIdx.y;
    const int* rp = sel ? g_rp2 : g_rp1;
    const int* es = sel ? g_es2 : g_es1;
    const float* evs = sel ? g_evv2 : g_evv1;
    const float2* in = sel ? reinterpret_cast<const float2*>(g_H2)
                           : reinterpret_cast<const float2*>(g_H1);
    float2* out = sel ? reinterpret_cast<float2*>(g_O2)
                      : reinterpret_cast<float2*>(g_O1);

    int start = rp[gw];
    int end   = rp[gw + 1];
    float2 acc = make_float2(0.f, 0.f);

    for (int j = start; j < end; j += 32) {
        int m = end - j;
        int iter = m < 32 ? m : 32;
        int s = 0; float v = 0.f;
        if (lane < iter) { s = es[j + lane]; v = evs[j + lane]; }
        for (int k = 0; k < iter; k++) {
            int   ss = __shfl_sync(0xffffffffu, s, k);
            float vv = __shfl_sync(0xffffffffu, v, k);
            if (lane < 20) {
                float2 h = in[(size_t)ss * 20 + lane];
                acc.x += vv * h.x;
                acc.y += vv * h.y;
            }
        }
    }
    if (lane < 20) out[(size_t)gw * 20 + lane] = acc;
}

// ---------------- fusion: gate + blend + log_softmax ----------------
__global__ void fuse_kernel(const float* __restrict__ b2,
                            const float* __restrict__ b4,
                            const float* __restrict__ Wl,
                            const float* __restrict__ bl,
                            float* __restrict__ out) {
    __shared__ float Wls[2 * NCLASS][NCLASS];
    __shared__ float b2s[NCLASS], b4s[NCLASS], bls[NCLASS];
    __shared__ float catS[8][2 * NCLASS];

    const int tid = threadIdx.x;
    const int lane = tid & 31;
    const int w = tid >> 5;

    for (int i = tid; i < 2 * NCLASS * NCLASS; i += 256)
        reinterpret_cast<float*>(Wls)[i] = Wl[i];
    if (tid < NCLASS) {
        b2s[tid] = b2[tid];
        b4s[tid] = b4[tid];
        bls[tid] = bl[tid];
    }
    __syncthreads();

    const int n = blockIdx.x * 8 + w;
    if (n >= N_NODES) return;

    for (int i = lane; i < NCLASS; i += 32) {
        catS[w][i]          = g_O1[(size_t)n * NCLASS + i] + b2s[i];
        catS[w][NCLASS + i] = g_O2[(size_t)n * NCLASS + i] + b4s[i];
    }
    __syncwarp();

    float v0, v1 = -1e30f;
    {
        int j = lane;
        float g = bls[j];
#pragma unroll
        for (int i = 0; i < 2 * NCLASS; i++) g += catS[w][i] * Wls[i][j];
        g = 1.f / (1.f + expf(-g));
        v0 = g * catS[w][j] + (1.f - g) * catS[w][NCLASS + j];
    }
    if (lane < 8) {
        int j = 32 + lane;
        float g = bls[j];
#pragma unroll
        for (int i = 0; i < 2 * NCLASS; i++) g += catS[w][i] * Wls[i][j];
        g = 1.f / (1.f + expf(-g));
        v1 = g * catS[w][j] + (1.f - g) * catS[w][NCLASS + j];
    }

    float m = fmaxf(v0, v1);
#pragma unroll
    for (int off = 16; off > 0; off >>= 1)
        m = fmaxf(m, __shfl_xor_sync(0xffffffffu, m, off));
    float s = expf(v0 - m) + (lane < 8 ? expf(v1 - m) : 0.f);
#pragma unroll
    for (int off = 16; off > 0; off >>= 1)
        s += __shfl_xor_sync(0xffffffffu, s, off);
    float ls = m + logf(s);

    out[(size_t)n * NCLASS + lane] = v0 - ls;
    if (lane < 8) out[(size_t)n * NCLASS + 32 + lane] = v1 - ls;
}

// ---------------- launch ----------------
extern "C" void kernel_launch(void* const* d_in, const int* in_sizes, int n_in,
                              void* d_out, int out_size) {
    const float* x   = (const float*)d_in[0];
    const int*   ei1 = (const int*)d_in[1];
    const float* ev1 = (const float*)d_in[2];
    const int*   ei2 = (const int*)d_in[3];
    const float* ev2 = (const float*)d_in[4];
    const float* W1  = (const float*)d_in[5];
    const float* b1  = (const float*)d_in[6];
    const float* W2  = (const float*)d_in[7];
    const float* b2  = (const float*)d_in[8];
    const float* W3  = (const float*)d_in[9];
    const float* b3  = (const float*)d_in[10];
    const float* W4  = (const float*)d_in[11];
    const float* b4  = (const float*)d_in[12];
    const float* Wl  = (const float*)d_in[13];
    const float* bl  = (const float*)d_in[14];
    float* out = (float*)d_out;

    const int EB = (E_EDGES + 255) / 256;

    // ---- CSR build for both edge lists ----
    zero_cnt_kernel<<<(N_NODES + 255) / 256, 256>>>();
    hist_kernel<<<dim3(EB, 2), 256>>>(ei1, ei2);
    scan_kernel<<<2, 1024>>>();
    scatter_kernel<<<dim3(EB, 2), 256>>>(ei1, ev1, ei2, ev2);

    // ---- GEMM1 (runs while CSR builds are independent of it — same stream,
    //      but GEMM1 doesn't depend on CSR; order chosen so scatter hides) --
    gemm512_tf32_kernel<<<dim3((N_NODES + 127) / 128, 2), 256>>>(x, W1, W3);

    // ---- SPMM over 128 features (CSR, no atomics) ----
    {
        int blocks = (N_NODES * 32 + 255) / 256;
        spmm128_csr_kernel<<<dim3(blocks, 2), 256>>>();
    }

    // ---- GEMM2 for both towers (relu+bias fused) ----
    gemm2_kernel<<<dim3((N_NODES + 63) / 64, 2), 256>>>(b1, W2, b3, W4);

    // ---- SPMM over 40 features (CSR, no atomics) ----
    {
        int blocks = (N_NODES * 32 + 255) / 256;
        spmm40_csr_kernel<<<dim3(blocks, 2), 256>>>();
    }

    // ---- gated fusion + log_softmax ----
    fuse_kernel<<<(N_NODES + 7) / 8, 256>>>(b2, b4, Wl, bl, out);
}

// round 10
// speedup vs baseline: 1.1215x; 1.1153x over previous
#include <cuda_runtime.h>
#include <math.h>
#include <stdint.h>

#define N_NODES 50000
#define E_EDGES 800000
#define NFEAT   512
#define NHID    128
#define NCLASS  40

// ---------------- scratch (device globals; no allocation) ----------------
__device__ __align__(16) float g_XW1[N_NODES * NHID];   // x @ W1
__device__ __align__(16) float g_XW3[N_NODES * NHID];   // x @ W3
__device__ __align__(16) float g_T1[N_NODES * NHID];    // spmm(adj , xW1)
__device__ __align__(16) float g_T3[N_NODES * NHID];    // spmm(adj2, xW3)
__device__ __align__(16) float g_H1[N_NODES * NCLASS];  // relu(T1+b1) @ W2
__device__ __align__(16) float g_H2[N_NODES * NCLASS];  // relu(T3+b3) @ W4
__device__ __align__(16) float g_O1[N_NODES * NCLASS];  // spmm(adj , H1)
__device__ __align__(16) float g_O2[N_NODES * NCLASS];  // spmm(adj2, H2)

// CSR scratch (per edge list)
__device__ int   g_cnt1[N_NODES],     g_cnt2[N_NODES];
__device__ int   g_rp1[N_NODES + 1],  g_rp2[N_NODES + 1];
__device__ int   g_cur1[N_NODES],     g_cur2[N_NODES];
__device__ int   g_es1[E_EDGES],      g_es2[E_EDGES];
__device__ float g_evv1[E_EDGES],     g_evv2[E_EDGES];

// ---------------- CSR build ----------------
__global__ void zero_cnt_kernel() {
    int i = blockIdx.x * blockDim.x + threadIdx.x;
    if (i < N_NODES) { g_cnt1[i] = 0; g_cnt2[i] = 0; }
}

__global__ void hist_kernel(const int* __restrict__ ei1,
                            const int* __restrict__ ei2) {
    int e = blockIdx.x * blockDim.x + threadIdx.x;
    if (e >= E_EDGES) return;
    int* cnt = blockIdx.y ? g_cnt2 : g_cnt1;
    const int* ei = blockIdx.y ? ei2 : ei1;
    atomicAdd(&cnt[ei[E_EDGES + e]], 1);
}

__global__ __launch_bounds__(1024) void scan_kernel() {
    const int list = blockIdx.x;
    __shared__ int sums[1024];
    const int tid = threadIdx.x;
    const int CHUNK = (N_NODES + 1023) / 1024;   // 49
    int begin = tid * CHUNK;
    int endi = begin + CHUNK; if (endi > N_NODES) endi = N_NODES;
    const int* cnt = list ? g_cnt2 : g_cnt1;
    int* rp  = list ? g_rp2  : g_rp1;
    int* cur = list ? g_cur2 : g_cur1;

    int s = 0;
    for (int i = begin; i < endi; i++) s += cnt[i];
    sums[tid] = s;
    __syncthreads();
    for (int off = 1; off < 1024; off <<= 1) {
        int v = sums[tid];
        int add = (tid >= off) ? sums[tid - off] : 0;
        __syncthreads();
        sums[tid] = v + add;
        __syncthreads();
    }
    int run = (tid == 0) ? 0 : sums[tid - 1];
    for (int i = begin; i < endi; i++) {
        int c = cnt[i];
        rp[i] = run; cur[i] = run;
        run += c;
    }
    if (tid == 1023) rp[N_NODES] = E_EDGES;
}

__global__ void scatter_kernel(const int* __restrict__ ei1,
                               const float* __restrict__ ev1,
                               const int* __restrict__ ei2,
                               const float* __restrict__ ev2) {
    int e = blockIdx.x * blockDim.x + threadIdx.x;
    if (e >= E_EDGES) return;
    const int sel = blockIdx.y;
    const int* ei = sel ? ei2 : ei1;
    const float* ev = sel ? ev2 : ev1;
    int* cur = sel ? g_cur2 : g_cur1;
    int* es  = sel ? g_es2  : g_es1;
    float* evs = sel ? g_evv2 : g_evv1;
    int s = ei[e];
    int d = ei[E_EDGES + e];
    int pos = atomicAdd(&cur[d], 1);
    es[pos] = s;
    evs[pos] = ev[e];
}

// ---------------- helpers ----------------
__device__ __forceinline__ float to_tf32(float f) {
    float r;
    asm("cvt.rna.tf32.f32 %0, %1;" : "=f"(r) : "f"(f));
    return r;
}
__device__ __forceinline__ uint32_t cvt_tf32(float f) {
    return __float_as_uint(to_tf32(f));
}
__device__ __forceinline__ void cp_async16(uint32_t dst_smem, const void* src, int src_bytes) {
    asm volatile("cp.async.cg.shared.global [%0], [%1], 16, %2;"
                 :: "r"(dst_smem), "l"(src), "r"(src_bytes));
}
__device__ __forceinline__ void cp_async_commit() {
    asm volatile("cp.async.commit_group;");
}
template<int N>
__device__ __forceinline__ void cp_async_wait() {
    asm volatile("cp.async.wait_group %0;" :: "n"(N));
}

// ---------------- GEMM1 (TF32 tensor cores, double-buffered cp.async) ----
// XW = x @ W  (M=50000, K=512, N=128)
// 128x128 block tile, 4 warps each 64x64, BK=16, 2-stage pipeline.
#define AP 20   // As row pitch (floats): 80B, 16B-aligned, conflict-free
#define BP 136  // Bs row pitch (floats): 544B, 16B-aligned, conflict-free
__global__ __launch_bounds__(128) void gemm512_tf32_kernel(
        const float* __restrict__ X,
        const float* __restrict__ W1,
        const float* __restrict__ W3) {
    const float* W   = blockIdx.y ? W3    : W1;
    float*       Out = blockIdx.y ? g_XW3 : g_XW1;

    __shared__ float As[2][128][AP];   // [buf][m][k] rows of X
    __shared__ float Bs[2][16][BP];    // [buf][k][n]

    const int tid  = threadIdx.x;
    const int lane = tid & 31;
    const int wid  = tid >> 5;          // 0..3
    const int mBase = (wid >> 1) * 64;
    const int nBase = (wid & 1) * 64;
    const int q = lane >> 2;            // 0..7
    const int c = lane & 3;             // 0..3
    const int rowBase = blockIdx.x * 128;

    float acc[4][8][4];
#pragma unroll
    for (int i = 0; i < 4; i++)
#pragma unroll
        for (int j = 0; j < 8; j++)
#pragma unroll
            for (int t = 0; t < 4; t++) acc[i][j][t] = 0.f;

    uint32_t asBase = (uint32_t)__cvta_generic_to_shared(&As[0][0][0]);
    uint32_t bsBase = (uint32_t)__cvta_generic_to_shared(&Bs[0][0][0]);

    // tile loader: A = 128 rows x 16 k (512 chunks), B = 16 k x 128 n (512)
    auto load_tile = [&](int buf, int k0) {
#pragma unroll
        for (int i = 0; i < 4; i++) {
            int li = tid + i * 128;         // 0..511
            int r  = li >> 2;               // 0..127
            int cc = (li & 3) << 2;         // 0,4,8,12
            int grow = rowBase + r;
            const float* src = X + (size_t)(grow < N_NODES ? grow : 0) * NFEAT + k0 + cc;
            uint32_t dst = asBase + (uint32_t)((buf * 128 + r) * AP + cc) * 4u;
            cp_async16(dst, src, grow < N_NODES ? 16 : 0);
        }
#pragma unroll
        for (int i = 0; i < 4; i++) {
            int li = tid + i * 128;         // 0..511
            int kr = li >> 5;               // 0..15
            int nc = (li & 31) << 2;        // 0..124
            const float* src = W + (size_t)(k0 + kr) * NHID + nc;
            uint32_t dst = bsBase + (uint32_t)((buf * 16 + kr) * BP + nc) * 4u;
            cp_async16(dst, src, 16);
        }
    };

    load_tile(0, 0);
    cp_async_commit();

    const int NK0 = NFEAT / 16;    // 32
    for (int k0i = 0; k0i < NK0; k0i++) {
        const int buf = k0i & 1;
        if (k0i + 1 < NK0) {
            load_tile(buf ^ 1, (k0i + 1) * 16);
            cp_async_commit();
            cp_async_wait<1>();
        } else {
            cp_async_wait<0>();
        }
        __syncthreads();

#pragma unroll
        for (int kk = 0; kk < 16; kk += 8) {
            uint32_t af[4][4];
#pragma unroll
            for (int i = 0; i < 4; i++) {
                int rA = mBase + i * 16 + q;
                af[i][0] = cvt_tf32(As[buf][rA    ][kk + c    ]);
                af[i][1] = cvt_tf32(As[buf][rA + 8][kk + c    ]);
                af[i][2] = cvt_tf32(As[buf][rA    ][kk + c + 4]);
                af[i][3] = cvt_tf32(As[buf][rA + 8][kk + c + 4]);
            }
            uint32_t bf[8][2];
#pragma unroll
            for (int j = 0; j < 8; j++) {
                int nC = nBase + j * 8 + q;
                bf[j][0] = cvt_tf32(Bs[buf][kk + c    ][nC]);
                bf[j][1] = cvt_tf32(Bs[buf][kk + c + 4][nC]);
            }
#pragma unroll
            for (int i = 0; i < 4; i++)
#pragma unroll
                for (int j = 0; j < 8; j++) {
                    asm volatile(
                        "mma.sync.aligned.m16n8k8.row.col.f32.tf32.tf32.f32 "
                        "{%0,%1,%2,%3}, {%4,%5,%6,%7}, {%8,%9}, {%0,%1,%2,%3};"
                        : "+f"(acc[i][j][0]), "+f"(acc[i][j][1]),
                          "+f"(acc[i][j][2]), "+f"(acc[i][j][3])
                        : "r"(af[i][0]), "r"(af[i][1]), "r"(af[i][2]), "r"(af[i][3]),
                          "r"(bf[j][0]), "r"(bf[j][1]));
                }
        }
        __syncthreads();
    }

    // ---- epilogue: float2 stores ----
#pragma unroll
    for (int i = 0; i < 4; i++) {
        int r0 = rowBase + mBase + i * 16 + q;
        int r1 = r0 + 8;
#pragma unroll
        for (int j = 0; j < 8; j++) {
            int col = nBase + j * 8 + 2 * c;
            if (r0 < N_NODES)
                *reinterpret_cast<float2*>(Out + (size_t)r0 * NHID + col)
                    = make_float2(acc[i][j][0], acc[i][j][1]);
            if (r1 < N_NODES)
                *reinterpret_cast<float2*>(Out + (size_t)r1 * NHID + col)
                    = make_float2(acc[i][j][2], acc[i][j][3]);
        }
    }
}

// ---------------- SPMM F=128 via CSR: warp per dst ----------------
__global__ void spmm128_csr_kernel() {
    int gw = (blockIdx.x * blockDim.x + threadIdx.x) >> 5;
    if (gw >= N_NODES) return;
    const int lane = threadIdx.x & 31;
    const int sel = blockIdx.y;
    const int* rp = sel ? g_rp2 : g_rp1;
    const int* es = sel ? g_es2 : g_es1;
    const float* evs = sel ? g_evv2 : g_evv1;
    const float4* in = sel ? reinterpret_cast<const float4*>(g_XW3)
                           : reinterpret_cast<const float4*>(g_XW1);
    float4* out = sel ? reinterpret_cast<float4*>(g_T3)
                      : reinterpret_cast<float4*>(g_T1);

    int start = rp[gw];
    int end   = rp[gw + 1];
    float4 acc = make_float4(0.f, 0.f, 0.f, 0.f);

    for (int j = start; j < end; j += 32) {
        int m = end - j;
        int iter = m < 32 ? m : 32;
        int s = 0; float v = 0.f;
        if (lane < iter) { s = es[j + lane]; v = evs[j + lane]; }
        for (int k = 0; k < iter; k++) {
            int   ss = __shfl_sync(0xffffffffu, s, k);
            float vv = __shfl_sync(0xffffffffu, v, k);
            float4 h = in[(size_t)ss * 32 + lane];
            acc.x += vv * h.x; acc.y += vv * h.y;
            acc.z += vv * h.z; acc.w += vv * h.w;
        }
    }
    out[(size_t)gw * 32 + lane] = acc;
}

// ---------------- GEMM2: H = relu(T + b) @ W  (K=128, N=40) ----------------
__global__ void gemm2_kernel(const float* __restrict__ b1,
                             const float* __restrict__ W2,
                             const float* __restrict__ b3,
                             const float* __restrict__ W4) {
    const int sel = blockIdx.y;
    const float* T = sel ? g_T3 : g_T1;
    const float* b = sel ? b3 : b1;
    const float* W = sel ? W4 : W2;
    float*      Out = sel ? g_H2 : g_H1;

    __shared__ float Ws[NHID][NCLASS];
    __shared__ float bs[NHID];
    __shared__ float Ts[64][17];

    const int tid = threadIdx.x;
    for (int i = tid; i < NHID * NCLASS; i += 256)
        reinterpret_cast<float*>(Ws)[i] = W[i];
    if (tid < NHID) bs[tid] = b[tid];
    __syncthreads();

    const int rowBase = blockIdx.x * 64;
    const int row = tid & 63;
    const int cg = tid >> 6;
    const int col0 = cg * 10;
    const int grow = rowBase + row;

    float acc[10];
#pragma unroll
    for (int j = 0; j < 10; j++) acc[j] = 0.f;

    for (int kb = 0; kb < NHID; kb += 16) {
#pragma unroll
        for (int i = 0; i < 4; i++) {
            int li = tid + i * 256;
            int r = li >> 4;
            int c = li & 15;
            int gr = rowBase + r;
            float v = 0.f;
            if (gr < N_NODES) v = T[(size_t)gr * NHID + kb + c];
            Ts[r][c] = fmaxf(v + bs[kb + c], 0.f);
        }
        __syncthreads();
#pragma unroll
        for (int kk = 0; kk < 16; kk++) {
            float h = Ts[row][kk];
#pragma unroll
            for (int j = 0; j < 10; j++)
                acc[j] += h * Ws[kb + kk][col0 + j];
        }
        __syncthreads();
    }

    if (grow < N_NODES) {
#pragma unroll
        for (int j = 0; j < 10; j++)
            Out[(size_t)grow * NCLASS + col0 + j] = acc[j];
    }
}

// ---------------- SPMM F=40 via CSR: warp per dst (float2 per lane) ------
__global__ void spmm40_csr_kernel() {
    int gw = (blockIdx.x * blockDim.x + threadIdx.x) >> 5;
    if (gw >= N_NODES) return;
    const int lane = threadIdx.x & 31;
    const int sel = blockIdx.y;
    const int* rp = sel ? g_rp2 : g_rp1;
    const int* es = sel ? g_es2 : g_es1;
    const float* evs = sel ? g_evv2 : g_evv1;
    const float2* in = sel ? reinterpret_cast<const float2*>(g_H2)
                           : reinterpret_cast<const float2*>(g_H1);
    float2* out = sel ? reinterpret_cast<float2*>(g_O2)
                      : reinterpret_cast<float2*>(g_O1);

    int start = rp[gw];
    int end   = rp[gw + 1];
    float2 acc = make_float2(0.f, 0.f);

    for (int j = start; j < end; j += 32) {
        int m = end - j;
        int iter = m < 32 ? m : 32;
        int s = 0; float v = 0.f;
        if (lane < iter) { s = es[j + lane]; v = evs[j + lane]; }
        for (int k = 0; k < iter; k++) {
            int   ss = __shfl_sync(0xffffffffu, s, k);
            float vv = __shfl_sync(0xffffffffu, v, k);
            if (lane < 20) {
                float2 h = in[(size_t)ss * 20 + lane];
                acc.x += vv * h.x;
                acc.y += vv * h.y;
            }
        }
    }
    if (lane < 20) out[(size_t)gw * 20 + lane] = acc;
}

// ---------------- fusion: gate + blend + log_softmax ----------------
__global__ void fuse_kernel(const float* __restrict__ b2,
                            const float* __restrict__ b4,
                            const float* __restrict__ Wl,
                            const float* __restrict__ bl,
                            float* __restrict__ out) {
    __shared__ float Wls[2 * NCLASS][NCLASS];
    __shared__ float b2s[NCLASS], b4s[NCLASS], bls[NCLASS];
    __shared__ float catS[8][2 * NCLASS];

    const int tid = threadIdx.x;
    const int lane = tid & 31;
    const int w = tid >> 5;

    for (int i = tid; i < 2 * NCLASS * NCLASS; i += 256)
        reinterpret_cast<float*>(Wls)[i] = Wl[i];
    if (tid < NCLASS) {
        b2s[tid] = b2[tid];
        b4s[tid] = b4[tid];
        bls[tid] = bl[tid];
    }
    __syncthreads();

    const int n = blockIdx.x * 8 + w;
    if (n >= N_NODES) return;

    for (int i = lane; i < NCLASS; i += 32) {
        catS[w][i]          = g_O1[(size_t)n * NCLASS + i] + b2s[i];
        catS[w][NCLASS + i] = g_O2[(size_t)n * NCLASS + i] + b4s[i];
    }
    __syncwarp();

    float v0, v1 = -1e30f;
    {
        int j = lane;
        float g = bls[j];
#pragma unroll
        for (int i = 0; i < 2 * NCLASS; i++) g += catS[w][i] * Wls[i][j];
        g = 1.f / (1.f + expf(-g));
        v0 = g * catS[w][j] + (1.f - g) * catS[w][NCLASS + j];
    }
    if (lane < 8) {
        int j = 32 + lane;
        float g = bls[j];
#pragma unroll
        for (int i = 0; i < 2 * NCLASS; i++) g += catS[w][i] * Wls[i][j];
        g = 1.f / (1.f + expf(-g));
        v1 = g * catS[w][j] + (1.f - g) * catS[w][NCLASS + j];
    }

    float m = fmaxf(v0, v1);
#pragma unroll
    for (int off = 16; off > 0; off >>= 1)
        m = fmaxf(m, __shfl_xor_sync(0xffffffffu, m, off));
    float s = expf(v0 - m) + (lane < 8 ? expf(v1 - m) : 0.f);
#pragma unroll
    for (int off = 16; off > 0; off >>= 1)
        s += __shfl_xor_sync(0xffffffffu, s, off);
    float ls = m + logf(s);

    out[(size_t)n * NCLASS + lane] = v0 - ls;
    if (lane < 8) out[(size_t)n * NCLASS + 32 + lane] = v1 - ls;
}

// ---------------- launch ----------------
extern "C" void kernel_launch(void* const* d_in, const int* in_sizes, int n_in,
                              void* d_out, int out_size) {
    const float* x   = (const float*)d_in[0];
    const int*   ei1 = (const int*)d_in[1];
    const float* ev1 = (const float*)d_in[2];
    const int*   ei2 = (const int*)d_in[3];
    const float* ev2 = (const float*)d_in[4];
    const float* W1  = (const float*)d_in[5];
    const float* b1  = (const float*)d_in[6];
    const float* W2  = (const float*)d_in[7];
    const float* b2  = (const float*)d_in[8];
    const float* W3  = (const float*)d_in[9];
    const float* b3  = (const float*)d_in[10];
    const float* W4  = (const float*)d_in[11];
    const float* b4  = (const float*)d_in[12];
    const float* Wl  = (const float*)d_in[13];
    const float* bl  = (const float*)d_in[14];
    float* out = (float*)d_out;

    const int EB = (E_EDGES + 255) / 256;

    // ---- CSR build for both edge lists ----
    zero_cnt_kernel<<<(N_NODES + 255) / 256, 256>>>();
    hist_kernel<<<dim3(EB, 2), 256>>>(ei1, ei2);
    scan_kernel<<<2, 1024>>>();
    scatter_kernel<<<dim3(EB, 2), 256>>>(ei1, ev1, ei2, ev2);

    // ---- GEMM1 (tf32 tensor cores, double-buffered) ----
    gemm512_tf32_kernel<<<dim3((N_NODES + 127) / 128, 2), 128>>>(x, W1, W3);

    // ---- SPMM over 128 features (CSR, no atomics) ----
    {
        int blocks = (N_NODES * 32 + 255) / 256;
        spmm128_csr_kernel<<<dim3(blocks, 2), 256>>>();
    }

    // ---- GEMM2 for both towers (relu+bias fused) ----
    gemm2_kernel<<<dim3((N_NODES + 63) / 64, 2), 256>>>(b1, W2, b3, W4);

    // ---- SPMM over 40 features (CSR, no atomics) ----
    {
        int blocks = (N_NODES * 32 + 255) / 256;
        spmm40_csr_kernel<<<dim3(blocks, 2), 256>>>();
    }

    // ---- gated fusion + log_softmax ----
    fuse_kernel<<<(N_NODES + 7) / 8, 256>>>(b2, b4, Wl, bl, out);
}

// round 12
// speedup vs baseline: 1.1391x; 1.0158x over previous
#include <cuda_runtime.h>
#include <math.h>
#include <stdint.h>

#define N_NODES 50000
#define E_EDGES 800000
#define NFEAT   512
#define NHID    128
#define NCLASS  40

// ---------------- scratch (device globals; no allocation) ----------------
__device__ __align__(16) float g_XW1[N_NODES * NHID];   // x @ W1
__device__ __align__(16) float g_XW3[N_NODES * NHID];   // x @ W3
__device__ __align__(16) float g_T1[N_NODES * NHID];    // spmm(adj , xW1)
__device__ __align__(16) float g_T3[N_NODES * NHID];    // spmm(adj2, xW3)
__device__ __align__(16) float g_H1[N_NODES * NCLASS];  // relu(T1+b1) @ W2
__device__ __align__(16) float g_H2[N_NODES * NCLASS];  // relu(T3+b3) @ W4
__device__ __align__(16) float g_O1[N_NODES * NCLASS];  // spmm(adj , H1)
__device__ __align__(16) float g_O2[N_NODES * NCLASS];  // spmm(adj2, H2)

// CSR scratch (per edge list)
__device__ int   g_cnt1[N_NODES],     g_cnt2[N_NODES];
__device__ int   g_rp1[N_NODES + 1],  g_rp2[N_NODES + 1];
__device__ int   g_cur1[N_NODES],     g_cur2[N_NODES];
__device__ int   g_es1[E_EDGES],      g_es2[E_EDGES];
__device__ float g_evv1[E_EDGES],     g_evv2[E_EDGES];

// ---------------- CSR build ----------------
__global__ void zero_cnt_kernel() {
    int i = blockIdx.x * blockDim.x + threadIdx.x;
    if (i < N_NODES) { g_cnt1[i] = 0; g_cnt2[i] = 0; }
}

__global__ void hist_kernel(const int* __restrict__ ei1,
                            const int* __restrict__ ei2) {
    int e = blockIdx.x * blockDim.x + threadIdx.x;
    if (e >= E_EDGES) return;
    int* cnt = blockIdx.y ? g_cnt2 : g_cnt1;
    const int* ei = blockIdx.y ? ei2 : ei1;
    atomicAdd(&cnt[ei[E_EDGES + e]], 1);
}

__global__ __launch_bounds__(1024) void scan_kernel() {
    const int list = blockIdx.x;
    __shared__ int sums[1024];
    const int tid = threadIdx.x;
    const int CHUNK = (N_NODES + 1023) / 1024;   // 49
    int begin = tid * CHUNK;
    int endi = begin + CHUNK; if (endi > N_NODES) endi = N_NODES;
    const int* cnt = list ? g_cnt2 : g_cnt1;
    int* rp  = list ? g_rp2  : g_rp1;
    int* cur = list ? g_cur2 : g_cur1;

    int s = 0;
    for (int i = begin; i < endi; i++) s += cnt[i];
    sums[tid] = s;
    __syncthreads();
    for (int off = 1; off < 1024; off <<= 1) {
        int v = sums[tid];
        int add = (tid >= off) ? sums[tid - off] : 0;
        __syncthreads();
        sums[tid] = v + add;
        __syncthreads();
    }
    int run = (tid == 0) ? 0 : sums[tid - 1];
    for (int i = begin; i < endi; i++) {
        int c = cnt[i];
        rp[i] = run; cur[i] = run;
        run += c;
    }
    if (tid == 1023) rp[N_NODES] = E_EDGES;
}

__global__ void scatter_kernel(const int* __restrict__ ei1,
                               const float* __restrict__ ev1,
                               const int* __restrict__ ei2,
                               const float* __restrict__ ev2) {
    int e = blockIdx.x * blockDim.x + threadIdx.x;
    if (e >= E_EDGES) return;
    const int sel = blockIdx.y;
    const int* ei = sel ? ei2 : ei1;
    const float* ev = sel ? ev2 : ev1;
    int* cur = sel ? g_cur2 : g_cur1;
    int* es  = sel ? g_es2  : g_es1;
    float* evs = sel ? g_evv2 : g_evv1;
    int s = ei[e];
    int d = ei[E_EDGES + e];
    int pos = atomicAdd(&cur[d], 1);
    es[pos] = s;
    evs[pos] = ev[e];
}

// ---------------- helpers ----------------
__device__ __forceinline__ float to_tf32(float f) {
    float r;
    asm("cvt.rna.tf32.f32 %0, %1;" : "=f"(r) : "f"(f));
    return r;
}
__device__ __forceinline__ uint32_t cvt_tf32(float f) {
    return __float_as_uint(to_tf32(f));
}
__device__ __forceinline__ void cp_async16(uint32_t dst_smem, const void* src, int src_bytes) {
    asm volatile("cp.async.cg.shared.global [%0], [%1], 16, %2;"
                 :: "r"(dst_smem), "l"(src), "r"(src_bytes));
}
__device__ __forceinline__ void cp_async_commit() {
    asm volatile("cp.async.commit_group;");
}
template<int N>
__device__ __forceinline__ void cp_async_wait() {
    asm volatile("cp.async.wait_group %0;" :: "n"(N));
}

// ---------------- GEMM1 (TF32 tensor cores, double-buffered cp.async) ----
#define AP 20   // As row pitch (floats)
#define BP 136  // Bs row pitch (floats)
__global__ __launch_bounds__(128) void gemm512_tf32_kernel(
        const float* __restrict__ X,
        const float* __restrict__ W1,
        const float* __restrict__ W3) {
    const float* W   = blockIdx.y ? W3    : W1;
    float*       Out = blockIdx.y ? g_XW3 : g_XW1;

    __shared__ float As[2][128][AP];
    __shared__ float Bs[2][16][BP];

    const int tid  = threadIdx.x;
    const int lane = tid & 31;
    const int wid  = tid >> 5;
    const int mBase = (wid >> 1) * 64;
    const int nBase = (wid & 1) * 64;
    const int q = lane >> 2;
    const int c = lane & 3;
    const int rowBase = blockIdx.x * 128;

    float acc[4][8][4];
#pragma unroll
    for (int i = 0; i < 4; i++)
#pragma unroll
        for (int j = 0; j < 8; j++)
#pragma unroll
            for (int t = 0; t < 4; t++) acc[i][j][t] = 0.f;

    uint32_t asBase = (uint32_t)__cvta_generic_to_shared(&As[0][0][0]);
    uint32_t bsBase = (uint32_t)__cvta_generic_to_shared(&Bs[0][0][0]);

    auto load_tile = [&](int buf, int k0) {
#pragma unroll
        for (int i = 0; i < 4; i++) {
            int li = tid + i * 128;
            int r  = li >> 2;
            int cc = (li & 3) << 2;
            int grow = rowBase + r;
            const float* src = X + (size_t)(grow < N_NODES ? grow : 0) * NFEAT + k0 + cc;
            uint32_t dst = asBase + (uint32_t)((buf * 128 + r) * AP + cc) * 4u;
            cp_async16(dst, src, grow < N_NODES ? 16 : 0);
        }
#pragma unroll
        for (int i = 0; i < 4; i++) {
            int li = tid + i * 128;
            int kr = li >> 5;
            int nc = (li & 31) << 2;
            const float* src = W + (size_t)(k0 + kr) * NHID + nc;
            uint32_t dst = bsBase + (uint32_t)((buf * 16 + kr) * BP + nc) * 4u;
            cp_async16(dst, src, 16);
        }
    };

    load_tile(0, 0);
    cp_async_commit();

    const int NK0 = NFEAT / 16;
    for (int k0i = 0; k0i < NK0; k0i++) {
        const int buf = k0i & 1;
        if (k0i + 1 < NK0) {
            load_tile(buf ^ 1, (k0i + 1) * 16);
            cp_async_commit();
            cp_async_wait<1>();
        } else {
            cp_async_wait<0>();
        }
        __syncthreads();

#pragma unroll
        for (int kk = 0; kk < 16; kk += 8) {
            uint32_t af[4][4];
#pragma unroll
            for (int i = 0; i < 4; i++) {
                int rA = mBase + i * 16 + q;
                af[i][0] = cvt_tf32(As[buf][rA    ][kk + c    ]);
                af[i][1] = cvt_tf32(As[buf][rA + 8][kk + c    ]);
                af[i][2] = cvt_tf32(As[buf][rA    ][kk + c + 4]);
                af[i][3] = cvt_tf32(As[buf][rA + 8][kk + c + 4]);
            }
            uint32_t bf[8][2];
#pragma unroll
            for (int j = 0; j < 8; j++) {
                int nC = nBase + j * 8 + q;
                bf[j][0] = cvt_tf32(Bs[buf][kk + c    ][nC]);
                bf[j][1] = cvt_tf32(Bs[buf][kk + c + 4][nC]);
            }
#pragma unroll
            for (int i = 0; i < 4; i++)
#pragma unroll
                for (int j = 0; j < 8; j++) {
                    asm volatile(
                        "mma.sync.aligned.m16n8k8.row.col.f32.tf32.tf32.f32 "
                        "{%0,%1,%2,%3}, {%4,%5,%6,%7}, {%8,%9}, {%0,%1,%2,%3};"
                        : "+f"(acc[i][j][0]), "+f"(acc[i][j][1]),
                          "+f"(acc[i][j][2]), "+f"(acc[i][j][3])
                        : "r"(af[i][0]), "r"(af[i][1]), "r"(af[i][2]), "r"(af[i][3]),
                          "r"(bf[j][0]), "r"(bf[j][1]));
                }
        }
        __syncthreads();
    }

#pragma unroll
    for (int i = 0; i < 4; i++) {
        int r0 = rowBase + mBase + i * 16 + q;
        int r1 = r0 + 8;
#pragma unroll
        for (int j = 0; j < 8; j++) {
            int col = nBase + j * 8 + 2 * c;
            if (r0 < N_NODES)
                *reinterpret_cast<float2*>(Out + (size_t)r0 * NHID + col)
                    = make_float2(acc[i][j][0], acc[i][j][1]);
            if (r1 < N_NODES)
                *reinterpret_cast<float2*>(Out + (size_t)r1 * NHID + col)
                    = make_float2(acc[i][j][2], acc[i][j][3]);
        }
    }
}

// ---------------- SPMM F=128 via CSR: warp per dst ----------------
__global__ void spmm128_csr_kernel(int sel) {
    int gw = (blockIdx.x * blockDim.x + threadIdx.x) >> 5;
    if (gw >= N_NODES) return;
    const int lane = threadIdx.x & 31;
    const int* rp = sel ? g_rp2 : g_rp1;
    const int* es = sel ? g_es2 : g_es1;
    const float* evs = sel ? g_evv2 : g_evv1;
    const float4* in = sel ? reinterpret_cast<const float4*>(g_XW3)
                           : reinterpret_cast<const float4*>(g_XW1);
    float4* out = sel ? reinterpret_cast<float4*>(g_T3)
                      : reinterpret_cast<float4*>(g_T1);

    int start = rp[gw];
    int end   = rp[gw + 1];
    float4 acc = make_float4(0.f, 0.f, 0.f, 0.f);

    for (int j = start; j < end; j += 32) {
        int m = end - j;
        int iter = m < 32 ? m : 32;
        int s = 0; float v = 0.f;
        if (lane < iter) { s = es[j + lane]; v = evs[j + lane]; }
        for (int k = 0; k < iter; k++) {
            int   ss = __shfl_sync(0xffffffffu, s, k);
            float vv = __shfl_sync(0xffffffffu, v, k);
            float4 h = in[(size_t)ss * 32 + lane];
            acc.x += vv * h.x; acc.y += vv * h.y;
            acc.z += vv * h.z; acc.w += vv * h.w;
        }
    }
    out[(size_t)gw * 32 + lane] = acc;
}

// ---------------- GEMM2: H = relu(T + b) @ W  (K=128, N=40) ----------------
__global__ void gemm2_kernel(int sel,
                             const float* __restrict__ b1,
                             const float* __restrict__ W2,
                             const float* __restrict__ b3,
                             const float* __restrict__ W4) {
    const float* T = sel ? g_T3 : g_T1;
    const float* b = sel ? b3 : b1;
    const float* W = sel ? W4 : W2;
    float*      Out = sel ? g_H2 : g_H1;

    __shared__ float Ws[NHID][NCLASS];
    __shared__ float bs[NHID];
    __shared__ float Ts[64][17];

    const int tid = threadIdx.x;
    for (int i = tid; i < NHID * NCLASS; i += 256)
        reinterpret_cast<float*>(Ws)[i] = W[i];
    if (tid < NHID) bs[tid] = b[tid];
    __syncthreads();

    const int rowBase = blockIdx.x * 64;
    const int row = tid & 63;
    const int cg = tid >> 6;
    const int col0 = cg * 10;
    const int grow = rowBase + row;

    float acc[10];
#pragma unroll
    for (int j = 0; j < 10; j++) acc[j] = 0.f;

    for (int kb = 0; kb < NHID; kb += 16) {
#pragma unroll
        for (int i = 0; i < 4; i++) {
            int li = tid + i * 256;
            int r = li >> 4;
            int c = li & 15;
            int gr = rowBase + r;
            float v = 0.f;
            if (gr < N_NODES) v = T[(size_t)gr * NHID + kb + c];
            Ts[r][c] = fmaxf(v + bs[kb + c], 0.f);
        }
        __syncthreads();
#pragma unroll
        for (int kk = 0; kk < 16; kk++) {
            float h = Ts[row][kk];
#pragma unroll
            for (int j = 0; j < 10; j++)
                acc[j] += h * Ws[kb + kk][col0 + j];
        }
        __syncthreads();
    }

    if (grow < N_NODES) {
#pragma unroll
        for (int j = 0; j < 10; j++)
            Out[(size_t)grow * NCLASS + col0 + j] = acc[j];
    }
}

// ---------------- SPMM F=40 via CSR: warp per dst (float2 per lane) ------
__global__ void spmm40_csr_kernel(int sel) {
    int gw = (blockIdx.x * blockDim.x + threadIdx.x) >> 5;
    if (gw >= N_NODES) return;
    const int lane = threadIdx.x & 31;
    const int* rp = sel ? g_rp2 : g_rp1;
    const int* es = sel ? g_es2 : g_es1;
    const float* evs = sel ? g_evv2 : g_evv1;
    const float2* in = sel ? reinterpret_cast<const float2*>(g_H2)
                           : reinterpret_cast<const float2*>(g_H1);
    float2* out = sel ? reinterpret_cast<float2*>(g_O2)
                      : reinterpret_cast<float2*>(g_O1);

    int start = rp[gw];
    int end   = rp[gw + 1];
    float2 acc = make_float2(0.f, 0.f);

    for (int j = start; j < end; j += 32) {
        int m = end - j;
        int iter = m < 32 ? m : 32;
        int s = 0; float v = 0.f;
        if (lane < iter) { s = es[j + lane]; v = evs[j + lane]; }
        for (int k = 0; k < iter; k++) {
            int   ss = __shfl_sync(0xffffffffu, s, k);
            float vv = __shfl_sync(0xffffffffu, v, k);
            if (lane < 20) {
                float2 h = in[(size_t)ss * 20 + lane];
                acc.x += vv * h.x;
                acc.y += vv * h.y;
            }
        }
    }
    if (lane < 20) out[(size_t)gw * 20 + lane] = acc;
}

// ---------------- fusion: gate + blend + log_softmax ----------------
__global__ void fuse_kernel(const float* __restrict__ b2,
                            const float* __restrict__ b4,
                            const float* __restrict__ Wl,
                            const float* __restrict__ bl,
                            float* __restrict__ out) {
    __shared__ float Wls[2 * NCLASS][NCLASS];
    __shared__ float b2s[NCLASS], b4s[NCLASS], bls[NCLASS];
    __shared__ float catS[8][2 * NCLASS];

    const int tid = threadIdx.x;
    const int lane = tid & 31;
    const int w = tid >> 5;

    for (int i = tid; i < 2 * NCLASS * NCLASS; i += 256)
        reinterpret_cast<float*>(Wls)[i] = Wl[i];
    if (tid < NCLASS) {
        b2s[tid] = b2[tid];
        b4s[tid] = b4[tid];
        bls[tid] = bl[tid];
    }
    __syncthreads();

    const int n = blockIdx.x * 8 + w;
    if (n >= N_NODES) return;

    for (int i = lane; i < NCLASS; i += 32) {
        catS[w][i]          = g_O1[(size_t)n * NCLASS + i] + b2s[i];
        catS[w][NCLASS + i] = g_O2[(size_t)n * NCLASS + i] + b4s[i];
    }
    __syncwarp();

    float v0, v1 = -1e30f;
    {
        int j = lane;
        float g = bls[j];
#pragma unroll
        for (int i = 0; i < 2 * NCLASS; i++) g += catS[w][i] * Wls[i][j];
        g = 1.f / (1.f + expf(-g));
        v0 = g * catS[w][j] + (1.f - g) * catS[w][NCLASS + j];
    }
    if (lane < 8) {
        int j = 32 + lane;
        float g = bls[j];
#pragma unroll
        for (int i = 0; i < 2 * NCLASS; i++) g += catS[w][i] * Wls[i][j];
        g = 1.f / (1.f + expf(-g));
        v1 = g * catS[w][j] + (1.f - g) * catS[w][NCLASS + j];
    }

    float m = fmaxf(v0, v1);
#pragma unroll
    for (int off = 16; off > 0; off >>= 1)
        m = fmaxf(m, __shfl_xor_sync(0xffffffffu, m, off));
    float s = expf(v0 - m) + (lane < 8 ? expf(v1 - m) : 0.f);
#pragma unroll
    for (int off = 16; off > 0; off >>= 1)
        s += __shfl_xor_sync(0xffffffffu, s, off);
    float ls = m + logf(s);

    out[(size_t)n * NCLASS + lane] = v0 - ls;
    if (lane < 8) out[(size_t)n * NCLASS + 32 + lane] = v1 - ls;
}

// ---------------- launch ----------------
extern "C" void kernel_launch(void* const* d_in, const int* in_sizes, int n_in,
                              void* d_out, int out_size) {
    const float* x   = (const float*)d_in[0];
    const int*   ei1 = (const int*)d_in[1];
    const float* ev1 = (const float*)d_in[2];
    const int*   ei2 = (const int*)d_in[3];
    const float* ev2 = (const float*)d_in[4];
    const float* W1  = (const float*)d_in[5];
    const float* b1  = (const float*)d_in[6];
    const float* W2  = (const float*)d_in[7];
    const float* b2  = (const float*)d_in[8];
    const float* W3  = (const float*)d_in[9];
    const float* b3  = (const float*)d_in[10];
    const float* W4  = (const float*)d_in[11];
    const float* b4  = (const float*)d_in[12];
    const float* Wl  = (const float*)d_in[13];
    const float* bl  = (const float*)d_in[14];
    float* out = (float*)d_out;

    // lazy one-time stream/event setup (host-side only; no device memory)
    static cudaStream_t sGemm = nullptr, sT2 = nullptr;
    static cudaEvent_t evFork = nullptr, evGemm = nullptr,
                       evCsr = nullptr, evT2 = nullptr;
    if (!sGemm) {
        cudaStreamCreateWithFlags(&sGemm, cudaStreamNonBlocking);
        cudaStreamCreateWithFlags(&sT2, cudaStreamNonBlocking);
        cudaEventCreateWithFlags(&evFork, cudaEventDisableTiming);
        cudaEventCreateWithFlags(&evGemm, cudaEventDisableTiming);
        cudaEventCreateWithFlags(&evCsr, cudaEventDisableTiming);
        cudaEventCreateWithFlags(&evT2, cudaEventDisableTiming);
    }

    const int EB = (E_EDGES + 255) / 256;
    const int SPB = (N_NODES * 32 + 255) / 256;

    // ---- fork: GEMM1 on side stream, CSR build on main stream ----
    cudaEventRecord(evFork, 0);
    cudaStreamWaitEvent(sGemm, evFork, 0);

    gemm512_tf32_kernel<<<dim3((N_NODES + 127) / 128, 2), 128, 0, sGemm>>>(x, W1, W3);
    cudaEventRecord(evGemm, sGemm);

    zero_cnt_kernel<<<(N_NODES + 255) / 256, 256>>>();
    hist_kernel<<<dim3(EB, 2), 256>>>(ei1, ei2);
    scan_kernel<<<2, 1024>>>();
    scatter_kernel<<<dim3(EB, 2), 256>>>(ei1, ev1, ei2, ev2);

    // join: both CSR + GEMM1 done before spmm
    cudaStreamWaitEvent(0, evGemm, 0);

    // ---- fork towers: tower1 on main, tower2 on sT2 ----
    cudaEventRecord(evCsr, 0);
    cudaStreamWaitEvent(sT2, evCsr, 0);

    // tower 1 (main stream)
    spmm128_csr_kernel<<<SPB, 256>>>(0);
    gemm2_kernel<<<(N_NODES + 63) / 64, 256>>>(0, b1, W2, b3, W4);
    spmm40_csr_kernel<<<SPB, 256>>>(0);

    // tower 2 (side stream)
    spmm128_csr_kernel<<<SPB, 256, 0, sT2>>>(1);
    gemm2_kernel<<<(N_NODES + 63) / 64, 256, 0, sT2>>>(1, b1, W2, b3, W4);
    spmm40_csr_kernel<<<SPB, 256, 0, sT2>>>(1);
    cudaEventRecord(evT2, sT2);

    // join before fuse
    cudaStreamWaitEvent(0, evT2, 0);

    // ---- gated fusion + log_softmax ----
    fuse_kernel<<<(N_NODES + 7) / 8, 256>>>(b2, b4, Wl, bl, out);
}

// round 16
// speedup vs baseline: 1.4347x; 1.2595x over previous
#include <cuda_runtime.h>
#include <math.h>
#include <stdint.h>

#define N_NODES 50000
#define E_EDGES 800000
#define NFEAT   512
#define NHID    128
#define NCLASS  40

// ---------------- scratch (device globals; no allocation) ----------------
__device__ __align__(16) float g_XW1[N_NODES * NHID];   // x @ W1
__device__ __align__(16) float g_XW3[N_NODES * NHID];   // x @ W3
__device__ __align__(16) float g_T1[N_NODES * NHID];    // spmm(adj , xW1)
__device__ __align__(16) float g_T3[N_NODES * NHID];    // spmm(adj2, xW3)
__device__ __align__(16) float g_H1[N_NODES * NCLASS];  // relu(T1+b1) @ W2
__device__ __align__(16) float g_H2[N_NODES * NCLASS];  // relu(T3+b3) @ W4
__device__ __align__(16) float g_O1[N_NODES * NCLASS];  // spmm(adj , H1)
__device__ __align__(16) float g_O2[N_NODES * NCLASS];  // spmm(adj2, H2)

// CSR scratch (per edge list)
__device__ int   g_cnt1[N_NODES],     g_cnt2[N_NODES];
__device__ int   g_rp1[N_NODES + 1],  g_rp2[N_NODES + 1];
__device__ int   g_cur1[N_NODES],     g_cur2[N_NODES];
__device__ int   g_es1[E_EDGES],      g_es2[E_EDGES];
__device__ float g_evv1[E_EDGES],     g_evv2[E_EDGES];

// hierarchical scan scratch
#define SCB 512
#define SNB ((N_NODES + SCB - 1) / SCB)   // 98
__device__ int g_bsum[2][SNB];

// ---------------- CSR build ----------------
__global__ void zero_cnt_kernel() {
    int i = blockIdx.x * blockDim.x + threadIdx.x;
    if (i < N_NODES) { g_cnt1[i] = 0; g_cnt2[i] = 0; }
}

__global__ void hist_kernel(const int* __restrict__ ei1,
                            const int* __restrict__ ei2) {
    int e = blockIdx.x * blockDim.x + threadIdx.x;
    if (e >= E_EDGES) return;
    int* cnt = blockIdx.y ? g_cnt2 : g_cnt1;
    const int* ei = blockIdx.y ? ei2 : ei1;
    atomicAdd(&cnt[ei[E_EDGES + e]], 1);
}

// pass1: per-block sums of 512 counters
__global__ __launch_bounds__(SCB) void scan_pass1() {
    __shared__ int red[SCB];
    const int list = blockIdx.y;
    const int tid = threadIdx.x;
    int i = blockIdx.x * SCB + tid;
    const int* cnt = list ? g_cnt2 : g_cnt1;
    red[tid] = (i < N_NODES) ? cnt[i] : 0;
    __syncthreads();
#pragma unroll
    for (int off = SCB / 2; off > 0; off >>= 1) {
        if (tid < off) red[tid] += red[tid + off];
        __syncthreads();
    }
    if (tid == 0) g_bsum[list][blockIdx.x] = red[0];
}

// pass2: serial exclusive scan of the 98 block sums (both lists), in smem
__global__ void scan_pass2() {
    __shared__ int s[2][SNB];
    const int tid = threadIdx.x;
    for (int i = tid; i < 2 * SNB; i += blockDim.x)
        s[i / SNB][i % SNB] = g_bsum[i / SNB][i % SNB];
    __syncthreads();
    if (tid < 2) {
        int run = 0;
        for (int i = 0; i < SNB; i++) { int c = s[tid][i]; s[tid][i] = run; run += c; }
    }
    __syncthreads();
    for (int i = tid; i < 2 * SNB; i += blockDim.x)
        g_bsum[i / SNB][i % SNB] = s[i / SNB][i % SNB];
}

// pass3: block-local Hillis-Steele + base offset -> rp, cur
__global__ __launch_bounds__(SCB) void scan_pass3() {
    __shared__ int s[SCB];
    const int list = blockIdx.y;
    const int tid = threadIdx.x;
    int i = blockIdx.x * SCB + tid;
    const int* cnt = list ? g_cnt2 : g_cnt1;
    int* rp  = list ? g_rp2  : g_rp1;
    int* cur = list ? g_cur2 : g_cur1;
    int v = (i < N_NODES) ? cnt[i] : 0;
    s[tid] = v;
    __syncthreads();
#pragma unroll
    for (int off = 1; off < SCB; off <<= 1) {
        int add = (tid >= off) ? s[tid - off] : 0;
        __syncthreads();
        s[tid] += add;
        __syncthreads();
    }
    if (i < N_NODES) {
        int ex = g_bsum[list][blockIdx.x] + s[tid] - v;  // exclusive prefix
        rp[i] = ex;
        cur[i] = ex;
    }
    if (i == N_NODES - 1) rp[N_NODES] = E_EDGES;
}

__global__ void scatter_kernel(const int* __restrict__ ei1,
                               const float* __restrict__ ev1,
                               const int* __restrict__ ei2,
                               const float* __restrict__ ev2) {
    int e = blockIdx.x * blockDim.x + threadIdx.x;
    if (e >= E_EDGES) return;
    const int sel = blockIdx.y;
    const int* ei = sel ? ei2 : ei1;
    const float* ev = sel ? ev2 : ev1;
    int* cur = sel ? g_cur2 : g_cur1;
    int* es  = sel ? g_es2  : g_es1;
    float* evs = sel ? g_evv2 : g_evv1;
    int s = ei[e];
    int d = ei[E_EDGES + e];
    int pos = atomicAdd(&cur[d], 1);
    es[pos] = s;
    evs[pos] = ev[e];
}

// ---------------- helpers ----------------
__device__ __forceinline__ void cp_async16(uint32_t dst_smem, const void* src, int src_bytes) {
    asm volatile("cp.async.cg.shared.global [%0], [%1], 16, %2;"
                 :: "r"(dst_smem), "l"(src), "r"(src_bytes));
}
__device__ __forceinline__ void cp_async_commit() {
    asm volatile("cp.async.commit_group;");
}
template<int N>
__device__ __forceinline__ void cp_async_wait() {
    asm volatile("cp.async.wait_group %0;" :: "n"(N));
}

// ---------------- GEMM1 (TF32 tensor cores, double-buffered cp.async) ----
// Raw f32 bits fed to mma.tf32 (HW truncation) — no cvt in the hot loop.
// Single __syncthreads per k-tile: wait -> sync -> issue next loads -> MMA.
#define AP 20   // As row pitch (floats)
#define BP 136  // Bs row pitch (floats)
__global__ __launch_bounds__(128) void gemm512_tf32_kernel(
        const float* __restrict__ X,
        const float* __restrict__ W1,
        const float* __restrict__ W3) {
    const float* W   = blockIdx.y ? W3    : W1;
    float*       Out = blockIdx.y ? g_XW3 : g_XW1;

    __shared__ float As[2][128][AP];
    __shared__ float Bs[2][16][BP];

    const int tid  = threadIdx.x;
    const int lane = tid & 31;
    const int wid  = tid >> 5;
    const int mBase = (wid >> 1) * 64;
    const int nBase = (wid & 1) * 64;
    const int q = lane >> 2;
    const int c = lane & 3;
    const int rowBase = blockIdx.x * 128;

    float acc[4][8][4];
#pragma unroll
    for (int i = 0; i < 4; i++)
#pragma unroll
        for (int j = 0; j < 8; j++)
#pragma unroll
            for (int t = 0; t < 4; t++) acc[i][j][t] = 0.f;

    uint32_t asBase = (uint32_t)__cvta_generic_to_shared(&As[0][0][0]);
    uint32_t bsBase = (uint32_t)__cvta_generic_to_shared(&Bs[0][0][0]);

    auto load_tile = [&](int buf, int k0) {
#pragma unroll
        for (int i = 0; i < 4; i++) {
            int li = tid + i * 128;
            int r  = li >> 2;
            int cc = (li & 3) << 2;
            int grow = rowBase + r;
            const float* src = X + (size_t)(grow < N_NODES ? grow : 0) * NFEAT + k0 + cc;
            uint32_t dst = asBase + (uint32_t)((buf * 128 + r) * AP + cc) * 4u;
            cp_async16(dst, src, grow < N_NODES ? 16 : 0);
        }
#pragma unroll
        for (int i = 0; i < 4; i++) {
            int li = tid + i * 128;
            int kr = li >> 5;
            int nc = (li & 31) << 2;
            const float* src = W + (size_t)(k0 + kr) * NHID + nc;
            uint32_t dst = bsBase + (uint32_t)((buf * 16 + kr) * BP + nc) * 4u;
            cp_async16(dst, src, 16);
        }
    };

    load_tile(0, 0);
    cp_async_commit();

    const int NK0 = NFEAT / 16;   // 32
    for (int k0i = 0; k0i < NK0; k0i++) {
        const int buf = k0i & 1;

        cp_async_wait<0>();
        __syncthreads();
        // safe: buf^1 was consumed in iteration k0i-1; sync above proves all
        // warps are done with it before we overwrite.
        if (k0i + 1 < NK0) {
            load_tile(buf ^ 1, (k0i + 1) * 16);
            cp_async_commit();
        }

#pragma unroll
        for (int kk = 0; kk < 16; kk += 8) {
            uint32_t af[4][4];
#pragma unroll
            for (int i = 0; i < 4; i++) {
                int rA = mBase + i * 16 + q;
                af[i][0] = __float_as_uint(As[buf][rA    ][kk + c    ]);
                af[i][1] = __float_as_uint(As[buf][rA + 8][kk + c    ]);
                af[i][2] = __float_as_uint(As[buf][rA    ][kk + c + 4]);
                af[i][3] = __float_as_uint(As[buf][rA + 8][kk + c + 4]);
            }
            uint32_t bf[8][2];
#pragma unroll
            for (int j = 0; j < 8; j++) {
                int nC = nBase + j * 8 + q;
                bf[j][0] = __float_as_uint(Bs[buf][kk + c    ][nC]);
                bf[j][1] = __float_as_uint(Bs[buf][kk + c + 4][nC]);
            }
#pragma unroll
            for (int i = 0; i < 4; i++)
#pragma unroll
                for (int j = 0; j < 8; j++) {
                    asm volatile(
                        "mma.sync.aligned.m16n8k8.row.col.f32.tf32.tf32.f32 "
                        "{%0,%1,%2,%3}, {%4,%5,%6,%7}, {%8,%9}, {%0,%1,%2,%3};"
                        : "+f"(acc[i][j][0]), "+f"(acc[i][j][1]),
                          "+f"(acc[i][j][2]), "+f"(acc[i][j][3])
                        : "r"(af[i][0]), "r"(af[i][1]), "r"(af[i][2]), "r"(af[i][3]),
                          "r"(bf[j][0]), "r"(bf[j][1]));
                }
        }
    }

#pragma unroll
    for (int i = 0; i < 4; i++) {
        int r0 = rowBase + mBase + i * 16 + q;
        int r1 = r0 + 8;
#pragma unroll
        for (int j = 0; j < 8; j++) {
            int col = nBase + j * 8 + 2 * c;
            if (r0 < N_NODES)
                *reinterpret_cast<float2*>(Out + (size_t)r0 * NHID + col)
                    = make_float2(acc[i][j][0], acc[i][j][1]);
            if (r1 < N_NODES)
                *reinterpret_cast<float2*>(Out + (size_t)r1 * NHID + col)
                    = make_float2(acc[i][j][2], acc[i][j][3]);
        }
    }
}

// ---------------- SPMM F=128 via CSR: warp per dst ----------------
__global__ void spmm128_csr_kernel(int sel) {
    int gw = (blockIdx.x * blockDim.x + threadIdx.x) >> 5;
    if (gw >= N_NODES) return;
    const int lane = threadIdx.x & 31;
    const int* rp = sel ? g_rp2 : g_rp1;
    const int* es = sel ? g_es2 : g_es1;
    const float* evs = sel ? g_evv2 : g_evv1;
    const float4* in = sel ? reinterpret_cast<const float4*>(g_XW3)
                           : reinterpret_cast<const float4*>(g_XW1);
    float4* out = sel ? reinterpret_cast<float4*>(g_T3)
                      : reinterpret_cast<float4*>(g_T1);

    int start = rp[gw];
    int end   = rp[gw + 1];
    float4 acc = make_float4(0.f, 0.f, 0.f, 0.f);

    for (int j = start; j < end; j += 32) {
        int m = end - j;
        int iter = m < 32 ? m : 32;
        int s = 0; float v = 0.f;
        if (lane < iter) { s = es[j + lane]; v = evs[j + lane]; }
        for (int k = 0; k < iter; k++) {
            int   ss = __shfl_sync(0xffffffffu, s, k);
            float vv = __shfl_sync(0xffffffffu, v, k);
            float4 h = in[(size_t)ss * 32 + lane];
            acc.x += vv * h.x; acc.y += vv * h.y;
            acc.z += vv * h.z; acc.w += vv * h.w;
        }
    }
    out[(size_t)gw * 32 + lane] = acc;
}

// ---------------- GEMM2: H = relu(T + b) @ W  (K=128, N=40) ----------------
__global__ void gemm2_kernel(int sel,
                             const float* __restrict__ b1,
                             const float* __restrict__ W2,
                             const float* __restrict__ b3,
                             const float* __restrict__ W4) {
    const float* T = sel ? g_T3 : g_T1;
    const float* b = sel ? b3 : b1;
    const float* W = sel ? W4 : W2;
    float*      Out = sel ? g_H2 : g_H1;

    __shared__ float Ws[NHID][NCLASS];
    __shared__ float bs[NHID];
    __shared__ float Ts[64][17];

    const int tid = threadIdx.x;
    for (int i = tid; i < NHID * NCLASS; i += 256)
        reinterpret_cast<float*>(Ws)[i] = W[i];
    if (tid < NHID) bs[tid] = b[tid];
    __syncthreads();

    const int rowBase = blockIdx.x * 64;
    const int row = tid & 63;
    const int cg = tid >> 6;
    const int col0 = cg * 10;
    const int grow = rowBase + row;

    float acc[10];
#pragma unroll
    for (int j = 0; j < 10; j++) acc[j] = 0.f;

    for (int kb = 0; kb < NHID; kb += 16) {
#pragma unroll
        for (int i = 0; i < 4; i++) {
            int li = tid + i * 256;
            int r = li >> 4;
            int c = li & 15;
            int gr = rowBase + r;
            float v = 0.f;
            if (gr < N_NODES) v = T[(size_t)gr * NHID + kb + c];
            Ts[r][c] = fmaxf(v + bs[kb + c], 0.f);
        }
        __syncthreads();
#pragma unroll
        for (int kk = 0; kk < 16; kk++) {
            float h = Ts[row][kk];
#pragma unroll
            for (int j = 0; j < 10; j++)
                acc[j] += h * Ws[kb + kk][col0 + j];
        }
        __syncthreads();
    }

    if (grow < N_NODES) {
#pragma unroll
        for (int j = 0; j < 10; j++)
            Out[(size_t)grow * NCLASS + col0 + j] = acc[j];
    }
}

// ---------------- SPMM F=40 via CSR: warp per dst (float2 per lane) ------
__global__ void spmm40_csr_kernel(int sel) {
    int gw = (blockIdx.x * blockDim.x + threadIdx.x) >> 5;
    if (gw >= N_NODES) return;
    const int lane = threadIdx.x & 31;
    const int* rp = sel ? g_rp2 : g_rp1;
    const int* es = sel ? g_es2 : g_es1;
    const float* evs = sel ? g_evv2 : g_evv1;
    const float2* in = sel ? reinterpret_cast<const float2*>(g_H2)
                           : reinterpret_cast<const float2*>(g_H1);
    float2* out = sel ? reinterpret_cast<float2*>(g_O2)
                      : reinterpret_cast<float2*>(g_O1);

    int start = rp[gw];
    int end   = rp[gw + 1];
    float2 acc = make_float2(0.f, 0.f);

    for (int j = start; j < end; j += 32) {
        int m = end - j;
        int iter = m < 32 ? m : 32;
        int s = 0; float v = 0.f;
        if (lane < iter) { s = es[j + lane]; v = evs[j + lane]; }
        for (int k = 0; k < iter; k++) {
            int   ss = __shfl_sync(0xffffffffu, s, k);
            float vv = __shfl_sync(0xffffffffu, v, k);
            if (lane < 20) {
                float2 h = in[(size_t)ss * 20 + lane];
                acc.x += vv * h.x;
                acc.y += vv * h.y;
            }
        }
    }
    if (lane < 20) out[(size_t)gw * 20 + lane] = acc;
}

// ---------------- fusion: gate + blend + log_softmax ----------------
__global__ void fuse_kernel(const float* __restrict__ b2,
                            const float* __restrict__ b4,
                            const float* __restrict__ Wl,
                            const float* __restrict__ bl,
                            float* __restrict__ out) {
    __shared__ float Wls[2 * NCLASS][NCLASS];
    __shared__ float b2s[NCLASS], b4s[NCLASS], bls[NCLASS];
    __shared__ float catS[8][2 * NCLASS];

    const int tid = threadIdx.x;
    const int lane = tid & 31;
    const int w = tid >> 5;

    for (int i = tid; i < 2 * NCLASS * NCLASS; i += 256)
        reinterpret_cast<float*>(Wls)[i] = Wl[i];
    if (tid < NCLASS) {
        b2s[tid] = b2[tid];
        b4s[tid] = b4[tid];
        bls[tid] = bl[tid];
    }
    __syncthreads();

    const int n = blockIdx.x * 8 + w;
    if (n >= N_NODES) return;

    for (int i = lane; i < NCLASS; i += 32) {
        catS[w][i]          = g_O1[(size_t)n * NCLASS + i] + b2s[i];
        catS[w][NCLASS + i] = g_O2[(size_t)n * NCLASS + i] + b4s[i];
    }
    __syncwarp();

    float v0, v1 = -1e30f;
    {
        int j = lane;
        float g = bls[j];
#pragma unroll
        for (int i = 0; i < 2 * NCLASS; i++) g += catS[w][i] * Wls[i][j];
        g = 1.f / (1.f + expf(-g));
        v0 = g * catS[w][j] + (1.f - g) * catS[w][NCLASS + j];
    }
    if (lane < 8) {
        int j = 32 + lane;
        float g = bls[j];
#pragma unroll
        for (int i = 0; i < 2 * NCLASS; i++) g += catS[w][i] * Wls[i][j];
        g = 1.f / (1.f + expf(-g));
        v1 = g * catS[w][j] + (1.f - g) * catS[w][NCLASS + j];
    }

    float m = fmaxf(v0, v1);
#pragma unroll
    for (int off = 16; off > 0; off >>= 1)
        m = fmaxf(m, __shfl_xor_sync(0xffffffffu, m, off));
    float s = expf(v0 - m) + (lane < 8 ? expf(v1 - m) : 0.f);
#pragma unroll
    for (int off = 16; off > 0; off >>= 1)
        s += __shfl_xor_sync(0xffffffffu, s, off);
    float ls = m + logf(s);

    out[(size_t)n * NCLASS + lane] = v0 - ls;
    if (lane < 8) out[(size_t)n * NCLASS + 32 + lane] = v1 - ls;
}

// ---------------- launch ----------------
extern "C" void kernel_launch(void* const* d_in, const int* in_sizes, int n_in,
                              void* d_out, int out_size) {
    const float* x   = (const float*)d_in[0];
    const int*   ei1 = (const int*)d_in[1];
    const float* ev1 = (const float*)d_in[2];
    const int*   ei2 = (const int*)d_in[3];
    const float* ev2 = (const float*)d_in[4];
    const float* W1  = (const float*)d_in[5];
    const float* b1  = (const float*)d_in[6];
    const float* W2  = (const float*)d_in[7];
    const float* b2  = (const float*)d_in[8];
    const float* W3  = (const float*)d_in[9];
    const float* b3  = (const float*)d_in[10];
    const float* W4  = (const float*)d_in[11];
    const float* b4  = (const float*)d_in[12];
    const float* Wl  = (const float*)d_in[13];
    const float* bl  = (const float*)d_in[14];
    float* out = (float*)d_out;

    // lazy one-time stream/event setup (host-side only; no device memory)
    static cudaStream_t sGemm = nullptr, sT2 = nullptr;
    static cudaEvent_t evFork = nullptr, evGemm = nullptr,
                       evCsr = nullptr, evT2 = nullptr;
    if (!sGemm) {
        cudaStreamCreateWithFlags(&sGemm, cudaStreamNonBlocking);
        cudaStreamCreateWithFlags(&sT2, cudaStreamNonBlocking);
        cudaEventCreateWithFlags(&evFork, cudaEventDisableTiming);
        cudaEventCreateWithFlags(&evGemm, cudaEventDisableTiming);
        cudaEventCreateWithFlags(&evCsr, cudaEventDisableTiming);
        cudaEventCreateWithFlags(&evT2, cudaEventDisableTiming);
    }

    const int EB = (E_EDGES + 255) / 256;
    const int SPB = (N_NODES * 32 + 255) / 256;

    // ---- fork: GEMM1 on side stream, CSR build on main stream ----
    cudaEventRecord(evFork, 0);
    cudaStreamWaitEvent(sGemm, evFork, 0);

    gemm512_tf32_kernel<<<dim3((N_NODES + 127) / 128, 2), 128, 0, sGemm>>>(x, W1, W3);
    cudaEventRecord(evGemm, sGemm);

    zero_cnt_kernel<<<(N_NODES + 255) / 256, 256>>>();
    hist_kernel<<<dim3(EB, 2), 256>>>(ei1, ei2);
    scan_pass1<<<dim3(SNB, 2), SCB>>>();
    scan_pass2<<<1, 256>>>();
    scan_pass3<<<dim3(SNB, 2), SCB>>>();
    scatter_kernel<<<dim3(EB, 2), 256>>>(ei1, ev1, ei2, ev2);

    // join: both CSR + GEMM1 done before spmm
    cudaStreamWaitEvent(0, evGemm, 0);

    // ---- fork towers: tower1 on main, tower2 on sT2 ----
    cudaEventRecord(evCsr, 0);
    cudaStreamWaitEvent(sT2, evCsr, 0);

    // tower 1 (main stream)
    spmm128_csr_kernel<<<SPB, 256>>>(0);
    gemm2_kernel<<<(N_NODES + 63) / 64, 256>>>(0, b1, W2, b3, W4);
    spmm40_csr_kernel<<<SPB, 256>>>(0);

    // tower 2 (side stream)
    spmm128_csr_kernel<<<SPB, 256, 0, sT2>>>(1);
    gemm2_kernel<<<(N_NODES + 63) / 64, 256, 0, sT2>>>(1, b1, W2, b3, W4);
    spmm40_csr_kernel<<<SPB, 256, 0, sT2>>>(1);
    cudaEventRecord(evT2, sT2);

    // join before fuse
    cudaStreamWaitEvent(0, evT2, 0);

    // ---- gated fusion + log_softmax ----
    fuse_kernel<<<(N_NODES + 7) / 8, 256>>>(b2, b4, Wl, bl, out);
}